// round 10
// baseline (speedup 1.0000x reference)
#include <cuda_runtime.h>
#include <math.h>

// Problem constants
#define NB 8
#define NL 1024
#define NC 1024
#define NH 16
#define ND 64

// Scratch (device globals — no allocation allowed)
__device__ float g_q[NB*NH*NL*ND];        // [B,H,L,D] fp32 (k_norm operates here)
__device__ float g_k[NB*NH*NL*ND];
__device__ float g_v[NB*NH*NL*ND];
__device__ unsigned g_xtf[NB*NL*NC];      // tf32(x)
__device__ unsigned g_wqkv_tf[3*NC*NC];   // tf32(w_qkv)
__device__ unsigned g_wproj_tf[NC*NC];    // tf32(w_proj)
__device__ unsigned g_kh[NB*NH*NL*ND];    // tf32(k) hi
__device__ unsigned g_kl[NB*NH*NL*ND];    // tf32(k - hi) lo
__device__ unsigned g_vt[NB*NH*ND*NL];    // tf32(v) transposed [b,h][d][l]
__device__ unsigned g_aotf[NB*NL*NC];     // tf32(attention out), [B,L,C]

// ---------------- TF32 tensor-core helpers ----------------------------------
static __device__ __forceinline__ unsigned f2tf(float f) {
    unsigned r;
    asm("cvt.rna.tf32.f32 %0, %1;" : "=r"(r) : "f"(f));
    return r;
}
static __device__ __forceinline__ void mma_tf32(float c[4], const unsigned a[4],
                                                const unsigned b[2]) {
    asm("mma.sync.aligned.m16n8k8.row.col.f32.tf32.tf32.f32 "
        "{%0,%1,%2,%3}, {%4,%5,%6,%7}, {%8,%9}, {%0,%1,%2,%3};"
        : "+f"(c[0]), "+f"(c[1]), "+f"(c[2]), "+f"(c[3])
        : "r"(a[0]), "r"(a[1]), "r"(a[2]), "r"(a[3]), "r"(b[0]), "r"(b[1]));
}

// ---------------- Prep kernels: hoist all f32->tf32 conversion --------------
__global__ void __launch_bounds__(256)
k_cvt3(const float4* __restrict__ x, const float4* __restrict__ wq,
       const float4* __restrict__ wp) {
    int i = blockIdx.x * blockDim.x + threadIdx.x;
    const int NX = NB*NL*NC/4;          // 2097152
    const int NW = 3*NC*NC/4;           // 786432
    const int NP = NC*NC/4;             // 262144
    float4 v; uint4* d;
    if (i < NX)                { v = x[i];            d = (uint4*)g_xtf + i; }
    else if (i < NX + NW)      { v = wq[i - NX];      d = (uint4*)g_wqkv_tf + (i - NX); }
    else if (i < NX + NW + NP) { v = wp[i - NX - NW]; d = (uint4*)g_wproj_tf + (i - NX - NW); }
    else return;
    *d = make_uint4(f2tf(v.x), f2tf(v.y), f2tf(v.z), f2tf(v.w));
}

// K -> hi/lo tf32 split (runs after k_norm)
__global__ void __launch_bounds__(256)
k_prep_khl() {
    int i = blockIdx.x * blockDim.x + threadIdx.x;   // float4 index, 2097152 total
    float4 v = ((const float4*)g_k)[i];
    uint4 h, l;
    h.x = f2tf(v.x); l.x = f2tf(v.x - __uint_as_float(h.x));
    h.y = f2tf(v.y); l.y = f2tf(v.y - __uint_as_float(h.y));
    h.z = f2tf(v.z); l.z = f2tf(v.z - __uint_as_float(h.z));
    h.w = f2tf(v.w); l.w = f2tf(v.w - __uint_as_float(h.w));
    ((uint4*)g_kh)[i] = h;
    ((uint4*)g_kl)[i] = l;
}

// V -> transposed tf32 [b,h][d][l]
__global__ void __launch_bounds__(256)
k_prep_vt() {
    int i = blockIdx.x * blockDim.x + threadIdx.x;   // output uint4 idx, 2097152
    int bh = i >> 14;          // 16384 uint4 per (b,h)
    int r  = i & 16383;
    int d  = r >> 8;           // 0..63
    int l4 = r & 255;          // l = l4*4
    const float* s = g_v + ((size_t)bh * NL + l4 * 4) * ND + d;
    uint4 o;
    o.x = f2tf(s[0]);
    o.y = f2tf(s[ND]);
    o.z = f2tf(s[2*ND]);
    o.w = f2tf(s[3*ND]);
    ((uint4*)g_vt)[i] = o;
}

// ---------------- TF32 NT GEMM core: 128x128 C-tile of A[M,K] * B[N,K]^T ----
// Inputs are pre-converted tf32 bit patterns (pure uint passthrough).
// 256 threads = 8 warps arranged 4(M) x 2(N); warp tile 32x64.
#define GPITCH 36
#define SM_BUF 4608                 // 128*36 words per tile buffer

__device__ __forceinline__ void gemm_tf32(const unsigned* __restrict__ A,
                                          const unsigned* __restrict__ Bw,
                                          int m0, int n0, int K,
                                          unsigned* sm, float acc[2][8][4]) {
    const int tid  = threadIdx.x;
    const int lane = tid & 31, wid = tid >> 5;
    const int wm = (wid & 3) << 5;           // warp m offset
    const int wn = (wid >> 2) << 6;          // warp n offset
    const int g  = lane >> 2, tg = lane & 3; // mma groupID / threadInGroup
    const int r0 = tid >> 3, slot = tid & 7; // loader: row base, uint4 slot

    unsigned* sA[2] = { sm,              sm + SM_BUF };
    unsigned* sB[2] = { sm + 2 * SM_BUF, sm + 3 * SM_BUF };

    const unsigned* pA = A  + (size_t)(m0 + r0) * K + slot * 4;
    const unsigned* pB = Bw + (size_t)(n0 + r0) * K + slot * 4;

    uint4 a4[4], b4[4];
    // prologue: tile 0 -> buf 0
    #pragma unroll
    for (int i = 0; i < 4; i++) {
        a4[i] = *(const uint4*)(pA + (size_t)(i * 32) * K);
        b4[i] = *(const uint4*)(pB + (size_t)(i * 32) * K);
    }
    #pragma unroll
    for (int i = 0; i < 4; i++) {
        *(uint4*)(sA[0] + (r0 + i * 32) * GPITCH + slot * 4) = a4[i];
        *(uint4*)(sB[0] + (r0 + i * 32) * GPITCH + slot * 4) = b4[i];
    }
    __syncthreads();

    const int NT = K >> 5;                   // BK = 32
    for (int kt = 0; kt < NT; kt++) {
        const int cur = kt & 1;
        if (kt + 1 < NT) {
            const unsigned* qA = pA + (kt + 1) * 32;
            const unsigned* qB = pB + (kt + 1) * 32;
            #pragma unroll
            for (int i = 0; i < 4; i++) {
                a4[i] = *(const uint4*)(qA + (size_t)(i * 32) * K);
                b4[i] = *(const uint4*)(qB + (size_t)(i * 32) * K);
            }
        }
        const unsigned* cA = sA[cur];
        const unsigned* cB = sB[cur];
        #pragma unroll
        for (int ks = 0; ks < 4; ks++) {
            const int k0 = ks * 8;
            unsigned af[2][4], bf[8][2];
            #pragma unroll
            for (int mt = 0; mt < 2; mt++) {
                const unsigned* p = cA + (wm + mt * 16 + g) * GPITCH + k0 + tg;
                af[mt][0] = p[0];
                af[mt][1] = p[8 * GPITCH];
                af[mt][2] = p[4];
                af[mt][3] = p[8 * GPITCH + 4];
            }
            #pragma unroll
            for (int nt = 0; nt < 8; nt++) {
                const unsigned* p = cB + (wn + nt * 8 + g) * GPITCH + k0 + tg;
                bf[nt][0] = p[0];
                bf[nt][1] = p[4];
            }
            #pragma unroll
            for (int mt = 0; mt < 2; mt++)
                #pragma unroll
                for (int nt = 0; nt < 8; nt++)
                    mma_tf32(acc[mt][nt], af[mt], bf[nt]);
        }
        if (kt + 1 < NT) {
            const int nxt = cur ^ 1;
            #pragma unroll
            for (int i = 0; i < 4; i++) {
                *(uint4*)(sA[nxt] + (r0 + i * 32) * GPITCH + slot * 4) = a4[i];
                *(uint4*)(sB[nxt] + (r0 + i * 32) * GPITCH + slot * 4) = b4[i];
            }
        }
        __syncthreads();
    }
}

// ---------------- Kernel 1: QKV GEMM (TF32) + bias + scatter to [B,H,L,D] ---
__global__ void __launch_bounds__(256)
k_qkv(const float* __restrict__ qb, const float* __restrict__ vb) {
    extern __shared__ unsigned smemu[];
    float acc[2][8][4];
    #pragma unroll
    for (int i = 0; i < 2; i++)
        #pragma unroll
        for (int j = 0; j < 8; j++)
            #pragma unroll
            for (int r = 0; r < 4; r++) acc[i][j][r] = 0.0f;

    const int n0 = blockIdx.x * 128;
    const int m0 = blockIdx.y * 128;
    gemm_tf32(g_xtf, g_wqkv_tf, m0, n0, NC, smemu, acc);

    const int lane = threadIdx.x & 31, wid = threadIdx.x >> 5;
    const int wm = (wid & 3) << 5, wn = (wid >> 2) << 6;
    const int g = lane >> 2, tg = lane & 3;

    #pragma unroll
    for (int mt = 0; mt < 2; mt++) {
        #pragma unroll
        for (int half = 0; half < 2; half++) {
            int m  = m0 + wm + mt * 16 + g + half * 8;
            int bb = m >> 10;
            int l  = m & 1023;
            #pragma unroll
            for (int nt = 0; nt < 8; nt++) {
                int n     = n0 + wn + nt * 8 + 2 * tg;
                int which = n >> 10;           // 0=q 1=k 2=v
                int cc    = n & 1023;
                int h     = cc >> 6;
                int dd    = cc & 63;
                float2 r;
                r.x = acc[mt][nt][half * 2 + 0];
                r.y = acc[mt][nt][half * 2 + 1];
                float* dst;
                if (which == 0) {
                    float2 b2 = *(const float2*)(qb + cc);
                    r.x += b2.x; r.y += b2.y;
                    dst = g_q;
                } else if (which == 1) {
                    dst = g_k;
                } else {
                    float2 b2 = *(const float2*)(vb + cc);
                    r.x += b2.x; r.y += b2.y;
                    dst = g_v;
                }
                *(float2*)(dst + (((size_t)bb * NH + h) * NL + l) * ND + dd) = r;
            }
        }
    }
}

// ---------------- Kernel 2: per-(b,h,l) L2 normalize of q (scaled) and k ----
__global__ void k_norm(const float* __restrict__ scale_mul) {
    const int lane = threadIdx.x & 31;
    const int row  = blockIdx.x * (blockDim.x >> 5) + (threadIdx.x >> 5);
    const int NQ   = NB * NH * NL;
    const bool isq = row < NQ;
    const int r    = isq ? row : row - NQ;
    float* base = (isq ? g_q : g_k) + (size_t)r * ND;
    float2 v = ((float2*)base)[lane];
    float ss = v.x * v.x + v.y * v.y;
    #pragma unroll
    for (int m = 16; m >= 1; m >>= 1)
        ss += __shfl_xor_sync(0xffffffffu, ss, m);
    float mul = 1.0f;
    if (isq) {
        int h = (r >> 10) & 15;
        mul = __expf(fminf(scale_mul[h], 4.605170185988091f)); // log(100)
    }
    float sc = mul / fmaxf(sqrtf(ss), 1e-12f);
    v.x *= sc; v.y *= sc;
    ((float2*)base)[lane] = v;
}

// ---------------- Kernel 3: flash attention (TF32 tensor cores) -------------
// Block = 128 threads (4 warps). Each warp owns 16 q rows; 64-wide KV tiles.
// QK^T uses 3xTF32 split (near-fp32); PV single TF32.
// K hi/lo and transposed V are pre-converted: loads are uint4 passthrough.
#define AP 68                      // smem pitch: (4g+tg) covers all 32 banks

__global__ void __launch_bounds__(128)
k_attn(const float* __restrict__ bias) {
    extern __shared__ unsigned smu[];
    unsigned* Kh = smu;                // [64][AP] tf32(K) hi
    unsigned* Kl = smu + 64 * AP;      // [64][AP] tf32(K) lo
    unsigned* Vt = smu + 2 * 64 * AP;  // [d][kv] transposed tf32(V)
    unsigned* Ps = smu + 3 * 64 * AP;  // [64 rows][AP] tf32(P)

    const int t    = threadIdx.x;
    const int lane = t & 31, w = t >> 5;
    const int g = lane >> 2, tg = lane & 3;
    const int bh = blockIdx.y, h = bh & 15;
    const int q0 = blockIdx.x * 64;
    const int r0 = w * 16 + g;        // block-local q row (this thread: r0, r0+8)

    // Q fragments, hi/lo split in-register (once per block)
    unsigned qh[8][4], ql[8][4];
    {
        const float* qbase = g_q + ((size_t)bh * NL + q0) * ND;
        #pragma unroll
        for (int kg = 0; kg < 8; kg++) {
            #pragma unroll
            for (int i = 0; i < 4; i++) {
                int row = r0 + (i & 1) * 8;
                int kk  = kg * 8 + tg + (i >> 1) * 4;
                float x = qbase[(size_t)row * ND + kk];
                unsigned xh = f2tf(x);
                qh[kg][i] = xh;
                ql[kg][i] = f2tf(x - __uint_as_float(xh));
            }
        }
    }

    float o[8][4];
    #pragma unroll
    for (int nt = 0; nt < 8; nt++)
        #pragma unroll
        for (int i = 0; i < 4; i++) o[nt][i] = 0.0f;
    float m0 = -INFINITY, m1 = -INFINITY, l0 = 0.0f, l1 = 0.0f;
    const float* bb = bias + (size_t)h * NL * NL;

    for (int j0 = 0; j0 < NL; j0 += 64) {
        __syncthreads();              // previous tile fully consumed
        // Pure uint4 passthrough loads (no cvt, no scalar scatter)
        {
            const uint4* khp = (const uint4*)(g_kh + ((size_t)bh * NL + j0) * ND);
            const uint4* klp = (const uint4*)(g_kl + ((size_t)bh * NL + j0) * ND);
            #pragma unroll
            for (int it = 0; it < 8; it++) {
                int idx = t + it * 128;          // [64 rows][16 uint4]
                int row = idx >> 4, c4 = (idx & 15) * 4;
                *(uint4*)(Kh + row * AP + c4) = khp[idx];
                *(uint4*)(Kl + row * AP + c4) = klp[idx];
            }
            const unsigned* vtb = g_vt + (size_t)bh * ND * NL + j0;
            #pragma unroll
            for (int it = 0; it < 8; it++) {
                int idx = t + it * 128;          // [64 d][16 uint4]
                int d = idx >> 4, c4 = (idx & 15) * 4;
                *(uint4*)(Vt + d * AP + c4) =
                    *(const uint4*)(vtb + (size_t)d * NL + c4);
            }
        }
        __syncthreads();

        // S = Q K^T (3xTF32 split)
        float s[8][4];
        #pragma unroll
        for (int nt = 0; nt < 8; nt++)
            #pragma unroll
            for (int i = 0; i < 4; i++) s[nt][i] = 0.0f;
        #pragma unroll
        for (int kg = 0; kg < 8; kg++) {
            #pragma unroll
            for (int nt = 0; nt < 8; nt++) {
                const unsigned* pk = Kh + (nt * 8 + g) * AP + kg * 8 + tg;
                const unsigned* pl = Kl + (nt * 8 + g) * AP + kg * 8 + tg;
                unsigned bh2[2] = { pk[0], pk[4] };
                unsigned bl2[2] = { pl[0], pl[4] };
                mma_tf32(s[nt], qh[kg], bh2);
                mma_tf32(s[nt], qh[kg], bl2);
                mma_tf32(s[nt], ql[kg], bh2);
            }
        }

        // bias add + tile max
        float tm0 = -INFINITY, tm1 = -INFINITY;
        #pragma unroll
        for (int nt = 0; nt < 8; nt++) {
            int col = j0 + nt * 8 + 2 * tg;
            float2 b0 = *(const float2*)(bb + (size_t)(q0 + r0) * NL + col);
            float2 b1 = *(const float2*)(bb + (size_t)(q0 + r0 + 8) * NL + col);
            s[nt][0] += b0.x; s[nt][1] += b0.y;
            s[nt][2] += b1.x; s[nt][3] += b1.y;
            tm0 = fmaxf(tm0, fmaxf(s[nt][0], s[nt][1]));
            tm1 = fmaxf(tm1, fmaxf(s[nt][2], s[nt][3]));
        }
        tm0 = fmaxf(tm0, __shfl_xor_sync(0xffffffffu, tm0, 1));
        tm0 = fmaxf(tm0, __shfl_xor_sync(0xffffffffu, tm0, 2));
        tm1 = fmaxf(tm1, __shfl_xor_sync(0xffffffffu, tm1, 1));
        tm1 = fmaxf(tm1, __shfl_xor_sync(0xffffffffu, tm1, 2));

        float mn0 = fmaxf(m0, tm0), mn1 = fmaxf(m1, tm1);
        float a0 = __expf(m0 - mn0), a1 = __expf(m1 - mn1);
        m0 = mn0; m1 = mn1;
        l0 *= a0; l1 *= a1;
        #pragma unroll
        for (int nt = 0; nt < 8; nt++) {
            o[nt][0] *= a0; o[nt][1] *= a0;
            o[nt][2] *= a1; o[nt][3] *= a1;
        }

        // p = exp(s - m); accumulate l; stage P into smem as tf32
        #pragma unroll
        for (int nt = 0; nt < 8; nt++) {
            float p0 = __expf(s[nt][0] - m0), p1 = __expf(s[nt][1] - m0);
            float p2 = __expf(s[nt][2] - m1), p3 = __expf(s[nt][3] - m1);
            l0 += p0 + p1; l1 += p2 + p3;
            unsigned* d0 = Ps + r0 * AP + nt * 8 + 2 * tg;
            unsigned* d1 = Ps + (r0 + 8) * AP + nt * 8 + 2 * tg;
            d0[0] = f2tf(p0); d0[1] = f2tf(p1);
            d1[0] = f2tf(p2); d1[1] = f2tf(p3);
        }
        __syncwarp();                  // Ps rows are warp-private

        // O += P V
        #pragma unroll
        for (int kg = 0; kg < 8; kg++) {
            const unsigned* pp = Ps + r0 * AP + kg * 8 + tg;
            const unsigned* pq = Ps + (r0 + 8) * AP + kg * 8 + tg;
            unsigned ap[4] = { pp[0], pq[0], pp[4], pq[4] };
            #pragma unroll
            for (int nt = 0; nt < 8; nt++) {
                const unsigned* pv = Vt + (nt * 8 + g) * AP + kg * 8 + tg;
                unsigned bv[2] = { pv[0], pv[4] };
                mma_tf32(o[nt], ap, bv);
            }
        }
    }

    // finish l reduction across tg and write out as tf32 bits (proj A operand)
    l0 += __shfl_xor_sync(0xffffffffu, l0, 1);
    l0 += __shfl_xor_sync(0xffffffffu, l0, 2);
    l1 += __shfl_xor_sync(0xffffffffu, l1, 1);
    l1 += __shfl_xor_sync(0xffffffffu, l1, 2);
    float i0 = 1.0f / l0, i1 = 1.0f / l1;

    unsigned* op = g_aotf + ((size_t)(bh >> 4) * NL + q0) * NC + h * ND;
    #pragma unroll
    for (int nt = 0; nt < 8; nt++) {
        int col = nt * 8 + 2 * tg;
        uint2 r0v = make_uint2(f2tf(o[nt][0] * i0), f2tf(o[nt][1] * i0));
        uint2 r1v = make_uint2(f2tf(o[nt][2] * i1), f2tf(o[nt][3] * i1));
        *(uint2*)(op + (size_t)r0 * NC + col)       = r0v;
        *(uint2*)(op + (size_t)(r0 + 8) * NC + col) = r1v;
    }
}

// ---------------- Kernel 4: output projection GEMM (TF32) + bias ------------
__global__ void __launch_bounds__(256)
k_proj(const float* __restrict__ bp, float* __restrict__ out) {
    extern __shared__ unsigned smemu[];
    float acc[2][8][4];
    #pragma unroll
    for (int i = 0; i < 2; i++)
        #pragma unroll
        for (int j = 0; j < 8; j++)
            #pragma unroll
            for (int r = 0; r < 4; r++) acc[i][j][r] = 0.0f;

    const int n0 = blockIdx.x * 128;
    const int m0 = blockIdx.y * 128;
    gemm_tf32(g_aotf, g_wproj_tf, m0, n0, NC, smemu, acc);

    const int lane = threadIdx.x & 31, wid = threadIdx.x >> 5;
    const int wm = (wid & 3) << 5, wn = (wid >> 2) << 6;
    const int g = lane >> 2, tg = lane & 3;

    #pragma unroll
    for (int mt = 0; mt < 2; mt++) {
        #pragma unroll
        for (int half = 0; half < 2; half++) {
            int m = m0 + wm + mt * 16 + g + half * 8;
            #pragma unroll
            for (int nt = 0; nt < 8; nt++) {
                int n = n0 + wn + nt * 8 + 2 * tg;
                float2 b2 = *(const float2*)(bp + n);
                float2 r;
                r.x = acc[mt][nt][half * 2 + 0] + b2.x;
                r.y = acc[mt][nt][half * 2 + 1] + b2.y;
                *(float2*)(out + (size_t)m * NC + n) = r;
            }
        }
    }
}

// ---------------- host launcher ---------------------------------------------
extern "C" void kernel_launch(void* const* d_in, const int* in_sizes, int n_in,
                              void* d_out, int out_size) {
    const float* x         = (const float*)d_in[0];
    const float* attn_bias = (const float*)d_in[1];
    const float* w_qkv     = (const float*)d_in[2];
    const float* q_bias    = (const float*)d_in[3];
    const float* v_bias    = (const float*)d_in[4];
    const float* scale_mul = (const float*)d_in[5];
    const float* w_proj    = (const float*)d_in[6];
    const float* b_proj    = (const float*)d_in[7];
    float* out = (float*)d_out;

    const int GEMM_SMEM = 4 * SM_BUF * 4;   // 73728 B (double-buffered A+B)
    cudaFuncSetAttribute(k_qkv,  cudaFuncAttributeMaxDynamicSharedMemorySize, GEMM_SMEM);
    cudaFuncSetAttribute(k_proj, cudaFuncAttributeMaxDynamicSharedMemorySize, GEMM_SMEM);

    // Pre-convert x, w_qkv, w_proj to tf32 bit patterns (hoisted from GEMMs)
    k_cvt3<<<12288, 256>>>((const float4*)x, (const float4*)w_qkv,
                           (const float4*)w_proj);

    // QKV projection: [8192,1024] x [3072,1024]^T (TF32 tensor cores)
    k_qkv<<<dim3(24, 64), 256, GEMM_SMEM>>>(q_bias, v_bias);

    // L2-normalize q (with exp(min(scale,log100)) scale) and k
    k_norm<<<32768, 256>>>(scale_mul);

    // Pre-split K into tf32 hi/lo and pre-transpose V (hoisted from k_attn)
    k_prep_khl<<<8192, 256>>>();
    k_prep_vt<<<8192, 256>>>();

    // attention: TF32 MMA flash attention, 64-row q tiles
    const int ATTN_SMEM = 4 * 64 * AP * 4;  // 69632 B
    cudaFuncSetAttribute(k_attn, cudaFuncAttributeMaxDynamicSharedMemorySize, ATTN_SMEM);
    k_attn<<<dim3(16, 128), 128, ATTN_SMEM>>>(attn_bias);

    // output projection: [8192,1024] x [1024,1024]^T (TF32 tensor cores)
    k_proj<<<dim3(8, 64), 256, GEMM_SMEM>>>(b_proj, out);
}

// round 12
// speedup vs baseline: 1.1915x; 1.1915x over previous
#include <cuda_runtime.h>
#include <cuda_bf16.h>
#include <math.h>

// Problem constants
#define NB 8
#define NL 1024
#define NC 1024
#define NH 16
#define ND 64

// Scratch (device globals — no allocation allowed)
__device__ float g_q[NB*NH*NL*ND];   // [B,H,L,D]
__device__ float g_k[NB*NH*NL*ND];
__device__ float g_v[NB*NH*NL*ND];
__device__ float g_ao[NB*NL*NC];     // attention output, [B,L,C]

// ---------------- TF32 / BF16 tensor-core helpers ---------------------------
static __device__ __forceinline__ unsigned f2tf(float f) {
    unsigned r;
    asm("cvt.rna.tf32.f32 %0, %1;" : "=r"(r) : "f"(f));
    return r;
}
static __device__ __forceinline__ void mma_tf32(float c[4], const unsigned a[4],
                                                const unsigned b[2]) {
    asm("mma.sync.aligned.m16n8k8.row.col.f32.tf32.tf32.f32 "
        "{%0,%1,%2,%3}, {%4,%5,%6,%7}, {%8,%9}, {%0,%1,%2,%3};"
        : "+f"(c[0]), "+f"(c[1]), "+f"(c[2]), "+f"(c[3])
        : "r"(a[0]), "r"(a[1]), "r"(a[2]), "r"(a[3]), "r"(b[0]), "r"(b[1]));
}
static __device__ __forceinline__ void mma_bf16(float c[4], const unsigned a[4],
                                                const unsigned b[2]) {
    asm("mma.sync.aligned.m16n8k16.row.col.f32.bf16.bf16.f32 "
        "{%0,%1,%2,%3}, {%4,%5,%6,%7}, {%8,%9}, {%0,%1,%2,%3};"
        : "+f"(c[0]), "+f"(c[1]), "+f"(c[2]), "+f"(c[3])
        : "r"(a[0]), "r"(a[1]), "r"(a[2]), "r"(a[3]), "r"(b[0]), "r"(b[1]));
}
// pack two floats into bf16x2 (x -> low half, y -> high half)
static __device__ __forceinline__ unsigned pk_bf2(float x, float y) {
    unsigned r;
    asm("cvt.rn.bf16x2.f32 %0, %1, %2;" : "=r"(r) : "f"(y), "f"(x));
    return r;
}
static __device__ __forceinline__ float bf_res(float x) {
    // residual x - bf16(x)
    __nv_bfloat16 h = __float2bfloat16(x);
    return x - __bfloat162float(h);
}

// ---------------- TF32 NT GEMM core: 128x128 C-tile of A[M,K] * B[N,K]^T ----
// 256 threads = 8 warps arranged 4(M) x 2(N); warp tile 32x64.
// Smem pitch 36 floats -> fragment loads are bank-conflict-free (4m+k).
#define GPITCH 36
#define SM_BUF 4608                 // 128*36 words per tile buffer

__device__ __forceinline__ void gemm_tf32(const float* __restrict__ A,
                                          const float* __restrict__ Bw,
                                          int m0, int n0, int K,
                                          unsigned* sm, float acc[2][8][4]) {
    const int tid  = threadIdx.x;
    const int lane = tid & 31, wid = tid >> 5;
    const int wm = (wid & 3) << 5;           // warp m offset
    const int wn = (wid >> 2) << 6;          // warp n offset
    const int g  = lane >> 2, tg = lane & 3; // mma groupID / threadInGroup
    const int r0 = tid >> 3, slot = tid & 7; // loader: row base, float4 slot

    unsigned* sA[2] = { sm,              sm + SM_BUF };
    unsigned* sB[2] = { sm + 2 * SM_BUF, sm + 3 * SM_BUF };

    const float* pA = A  + (size_t)(m0 + r0) * K + slot * 4;
    const float* pB = Bw + (size_t)(n0 + r0) * K + slot * 4;

    float4 a4[4], b4[4];
    // prologue: tile 0 -> buf 0
    #pragma unroll
    for (int i = 0; i < 4; i++) {
        a4[i] = *(const float4*)(pA + (size_t)(i * 32) * K);
        b4[i] = *(const float4*)(pB + (size_t)(i * 32) * K);
    }
    #pragma unroll
    for (int i = 0; i < 4; i++) {
        uint4 ua = make_uint4(f2tf(a4[i].x), f2tf(a4[i].y), f2tf(a4[i].z), f2tf(a4[i].w));
        uint4 ub = make_uint4(f2tf(b4[i].x), f2tf(b4[i].y), f2tf(b4[i].z), f2tf(b4[i].w));
        *(uint4*)(sA[0] + (r0 + i * 32) * GPITCH + slot * 4) = ua;
        *(uint4*)(sB[0] + (r0 + i * 32) * GPITCH + slot * 4) = ub;
    }
    __syncthreads();

    const int NT = K >> 5;                   // BK = 32
    for (int kt = 0; kt < NT; kt++) {
        const int cur = kt & 1;
        if (kt + 1 < NT) {
            const float* qA = pA + (kt + 1) * 32;
            const float* qB = pB + (kt + 1) * 32;
            #pragma unroll
            for (int i = 0; i < 4; i++) {
                a4[i] = *(const float4*)(qA + (size_t)(i * 32) * K);
                b4[i] = *(const float4*)(qB + (size_t)(i * 32) * K);
            }
        }
        const unsigned* cA = sA[cur];
        const unsigned* cB = sB[cur];
        #pragma unroll
        for (int ks = 0; ks < 4; ks++) {
            const int k0 = ks * 8;
            unsigned af[2][4], bf[8][2];
            #pragma unroll
            for (int mt = 0; mt < 2; mt++) {
                const unsigned* p = cA + (wm + mt * 16 + g) * GPITCH + k0 + tg;
                af[mt][0] = p[0];
                af[mt][1] = p[8 * GPITCH];
                af[mt][2] = p[4];
                af[mt][3] = p[8 * GPITCH + 4];
            }
            #pragma unroll
            for (int nt = 0; nt < 8; nt++) {
                const unsigned* p = cB + (wn + nt * 8 + g) * GPITCH + k0 + tg;
                bf[nt][0] = p[0];
                bf[nt][1] = p[4];
            }
            #pragma unroll
            for (int mt = 0; mt < 2; mt++)
                #pragma unroll
                for (int nt = 0; nt < 8; nt++)
                    mma_tf32(acc[mt][nt], af[mt], bf[nt]);
        }
        if (kt + 1 < NT) {
            const int nxt = cur ^ 1;
            #pragma unroll
            for (int i = 0; i < 4; i++) {
                uint4 ua = make_uint4(f2tf(a4[i].x), f2tf(a4[i].y), f2tf(a4[i].z), f2tf(a4[i].w));
                uint4 ub = make_uint4(f2tf(b4[i].x), f2tf(b4[i].y), f2tf(b4[i].z), f2tf(b4[i].w));
                *(uint4*)(sA[nxt] + (r0 + i * 32) * GPITCH + slot * 4) = ua;
                *(uint4*)(sB[nxt] + (r0 + i * 32) * GPITCH + slot * 4) = ub;
            }
        }
        __syncthreads();
    }
}

// ---------------- Kernel 1: QKV GEMM (TF32) + bias + scatter to [B,H,L,D] ---
__global__ void __launch_bounds__(256)
k_qkv(const float* __restrict__ x, const float* __restrict__ w,
      const float* __restrict__ qb, const float* __restrict__ vb) {
    extern __shared__ unsigned smemu[];
    float acc[2][8][4];
    #pragma unroll
    for (int i = 0; i < 2; i++)
        #pragma unroll
        for (int j = 0; j < 8; j++)
            #pragma unroll
            for (int r = 0; r < 4; r++) acc[i][j][r] = 0.0f;

    const int n0 = blockIdx.x * 128;
    const int m0 = blockIdx.y * 128;
    gemm_tf32(x, w, m0, n0, NC, smemu, acc);

    const int lane = threadIdx.x & 31, wid = threadIdx.x >> 5;
    const int wm = (wid & 3) << 5, wn = (wid >> 2) << 6;
    const int g = lane >> 2, tg = lane & 3;

    #pragma unroll
    for (int mt = 0; mt < 2; mt++) {
        #pragma unroll
        for (int half = 0; half < 2; half++) {
            int m  = m0 + wm + mt * 16 + g + half * 8;
            int bb = m >> 10;
            int l  = m & 1023;
            #pragma unroll
            for (int nt = 0; nt < 8; nt++) {
                int n     = n0 + wn + nt * 8 + 2 * tg;
                int which = n >> 10;           // 0=q 1=k 2=v
                int cc    = n & 1023;
                int h     = cc >> 6;
                int dd    = cc & 63;
                float2 r;
                r.x = acc[mt][nt][half * 2 + 0];
                r.y = acc[mt][nt][half * 2 + 1];
                float* dst;
                if (which == 0) {
                    float2 b2 = *(const float2*)(qb + cc);
                    r.x += b2.x; r.y += b2.y;
                    dst = g_q;
                } else if (which == 1) {
                    dst = g_k;
                } else {
                    float2 b2 = *(const float2*)(vb + cc);
                    r.x += b2.x; r.y += b2.y;
                    dst = g_v;
                }
                *(float2*)(dst + (((size_t)bb * NH + h) * NL + l) * ND + dd) = r;
            }
        }
    }
}

// ---------------- Kernel 2: per-(b,h,l) L2 normalize of q (scaled) and k ----
__global__ void k_norm(const float* __restrict__ scale_mul) {
    const int lane = threadIdx.x & 31;
    const int row  = blockIdx.x * (blockDim.x >> 5) + (threadIdx.x >> 5);
    const int NQ   = NB * NH * NL;
    const bool isq = row < NQ;
    const int r    = isq ? row : row - NQ;
    float* base = (isq ? g_q : g_k) + (size_t)r * ND;
    float2 v = ((float2*)base)[lane];
    float ss = v.x * v.x + v.y * v.y;
    #pragma unroll
    for (int m = 16; m >= 1; m >>= 1)
        ss += __shfl_xor_sync(0xffffffffu, ss, m);
    float mul = 1.0f;
    if (isq) {
        int h = (r >> 10) & 15;
        mul = __expf(fminf(scale_mul[h], 4.605170185988091f)); // log(100)
    }
    float sc = mul / fmaxf(sqrtf(ss), 1e-12f);
    v.x *= sc; v.y *= sc;
    ((float2*)base)[lane] = v;
}

// ---------------- Kernel 3: flash attention ---------------------------------
// QK^T: bf16 m16n8k16 with hi/lo split (QhKh + QlKh + QhKl) — half the MMA
// count of the 3xTF32 k8 scheme at ~4e-5 absolute S error.
// PV: tf32 m16n8k8 single (dominates rel_err at ~5e-4, within budget).
// Block = 128 threads (4 warps); each warp owns 16 q rows; 64-wide KV tiles.
#define KP 36                      // bf16x2 K-tile pitch (uints per row)
#define AP 68                      // tf32 V/P pitch (floats per row)

__global__ void __launch_bounds__(128)
k_attn(const float* __restrict__ bias) {
    extern __shared__ unsigned smu[];
    unsigned* Khs = smu;                     // [64][KP] bf16x2 hi(K)
    unsigned* Kls = smu + 64 * KP;           // [64][KP] bf16x2 lo(K)
    unsigned* Vt  = smu + 2 * 64 * KP;       // [64 d][AP] tf32(V) transposed
    unsigned* Ps  = smu + 2 * 64 * KP + 64 * AP;  // [64 rows][AP] tf32(P)

    const int t    = threadIdx.x;
    const int lane = t & 31, w = t >> 5;
    const int g = lane >> 2, tg = lane & 3;
    const int bh = blockIdx.y, h = bh & 15;
    const int q0 = blockIdx.x * 64;
    const int r0 = w * 16 + g;        // block-local q row (this thread: r0, r0+8)

    // Q fragments: bf16x2 hi/lo, m16n8k16 A-layout, resident all loop
    unsigned qh[4][4], ql[4][4];
    {
        const float* qbase = g_q + ((size_t)bh * NL + q0) * ND;
        #pragma unroll
        for (int kg = 0; kg < 4; kg++) {
            #pragma unroll
            for (int i = 0; i < 4; i++) {
                int row = r0 + (i & 1) * 8;
                int kk  = kg * 16 + 2 * tg + (i >> 1) * 8;
                float x0 = qbase[(size_t)row * ND + kk];
                float x1 = qbase[(size_t)row * ND + kk + 1];
                qh[kg][i] = pk_bf2(x0, x1);
                ql[kg][i] = pk_bf2(bf_res(x0), bf_res(x1));
            }
        }
    }

    float o[8][4];
    #pragma unroll
    for (int nt = 0; nt < 8; nt++)
        #pragma unroll
        for (int i = 0; i < 4; i++) o[nt][i] = 0.0f;
    float m0 = -INFINITY, m1 = -INFINITY, l0 = 0.0f, l1 = 0.0f;
    const float* bb = bias + (size_t)h * NL * NL;

    for (int j0 = 0; j0 < NL; j0 += 64) {
        __syncthreads();              // previous tile fully consumed
        // Load K tile (bf16x2 hi/lo) and V tile (transposed tf32)
        {
            const float* kp = g_k + ((size_t)bh * NL + j0) * ND;
            const float* vp = g_v + ((size_t)bh * NL + j0) * ND;
            #pragma unroll
            for (int it = 0; it < 8; it++) {
                int idx = t + it * 128;          // 1024 float4 slots
                int row = idx >> 4, c4 = (idx & 15) * 4;
                float4 k4 = *(const float4*)(kp + (size_t)row * ND + c4);
                float4 v4 = *(const float4*)(vp + (size_t)row * ND + c4);
                unsigned* kh = Khs + row * KP + (c4 >> 1);
                unsigned* kl = Kls + row * KP + (c4 >> 1);
                kh[0] = pk_bf2(k4.x, k4.y);
                kh[1] = pk_bf2(k4.z, k4.w);
                kl[0] = pk_bf2(bf_res(k4.x), bf_res(k4.y));
                kl[1] = pk_bf2(bf_res(k4.z), bf_res(k4.w));
                float vf[4] = {v4.x, v4.y, v4.z, v4.w};
                #pragma unroll
                for (int i = 0; i < 4; i++)
                    Vt[(c4 + i) * AP + row] = f2tf(vf[i]);
            }
        }
        __syncthreads();

        // S = Q K^T : bf16 k16, 3-term hi/lo split
        float s[8][4];
        #pragma unroll
        for (int nt = 0; nt < 8; nt++)
            #pragma unroll
            for (int i = 0; i < 4; i++) s[nt][i] = 0.0f;
        #pragma unroll
        for (int kg = 0; kg < 4; kg++) {
            #pragma unroll
            for (int nt = 0; nt < 8; nt++) {
                const unsigned* ph = Khs + (nt * 8 + g) * KP + kg * 8 + tg;
                const unsigned* pl = Kls + (nt * 8 + g) * KP + kg * 8 + tg;
                unsigned bh2[2] = { ph[0], ph[4] };
                unsigned bl2[2] = { pl[0], pl[4] };
                mma_bf16(s[nt], qh[kg], bh2);
                mma_bf16(s[nt], ql[kg], bh2);
                mma_bf16(s[nt], qh[kg], bl2);
            }
        }

        // bias add + tile max
        float tm0 = -INFINITY, tm1 = -INFINITY;
        #pragma unroll
        for (int nt = 0; nt < 8; nt++) {
            int col = j0 + nt * 8 + 2 * tg;
            float2 b0 = *(const float2*)(bb + (size_t)(q0 + r0) * NL + col);
            float2 b1 = *(const float2*)(bb + (size_t)(q0 + r0 + 8) * NL + col);
            s[nt][0] += b0.x; s[nt][1] += b0.y;
            s[nt][2] += b1.x; s[nt][3] += b1.y;
            tm0 = fmaxf(tm0, fmaxf(s[nt][0], s[nt][1]));
            tm1 = fmaxf(tm1, fmaxf(s[nt][2], s[nt][3]));
        }
        tm0 = fmaxf(tm0, __shfl_xor_sync(0xffffffffu, tm0, 1));
        tm0 = fmaxf(tm0, __shfl_xor_sync(0xffffffffu, tm0, 2));
        tm1 = fmaxf(tm1, __shfl_xor_sync(0xffffffffu, tm1, 1));
        tm1 = fmaxf(tm1, __shfl_xor_sync(0xffffffffu, tm1, 2));

        float mn0 = fmaxf(m0, tm0), mn1 = fmaxf(m1, tm1);
        float a0 = __expf(m0 - mn0), a1 = __expf(m1 - mn1);
        m0 = mn0; m1 = mn1;
        l0 *= a0; l1 *= a1;
        #pragma unroll
        for (int nt = 0; nt < 8; nt++) {
            o[nt][0] *= a0; o[nt][1] *= a0;
            o[nt][2] *= a1; o[nt][3] *= a1;
        }

        // p = exp(s - m); accumulate l; stage P into smem as tf32
        #pragma unroll
        for (int nt = 0; nt < 8; nt++) {
            float p0 = __expf(s[nt][0] - m0), p1 = __expf(s[nt][1] - m0);
            float p2 = __expf(s[nt][2] - m1), p3 = __expf(s[nt][3] - m1);
            l0 += p0 + p1; l1 += p2 + p3;
            unsigned* d0 = Ps + r0 * AP + nt * 8 + 2 * tg;
            unsigned* d1 = Ps + (r0 + 8) * AP + nt * 8 + 2 * tg;
            d0[0] = f2tf(p0); d0[1] = f2tf(p1);
            d1[0] = f2tf(p2); d1[1] = f2tf(p3);
        }
        __syncwarp();                  // Ps rows are warp-private

        // O += P V (tf32 k8)
        #pragma unroll
        for (int kg = 0; kg < 8; kg++) {
            const unsigned* pp = Ps + r0 * AP + kg * 8 + tg;
            const unsigned* pq = Ps + (r0 + 8) * AP + kg * 8 + tg;
            unsigned ap[4] = { pp[0], pq[0], pp[4], pq[4] };
            #pragma unroll
            for (int nt = 0; nt < 8; nt++) {
                const unsigned* pv = Vt + (nt * 8 + g) * AP + kg * 8 + tg;
                unsigned bv[2] = { pv[0], pv[4] };
                mma_tf32(o[nt], ap, bv);
            }
        }
    }

    // finish l reduction across tg and write out
    l0 += __shfl_xor_sync(0xffffffffu, l0, 1);
    l0 += __shfl_xor_sync(0xffffffffu, l0, 2);
    l1 += __shfl_xor_sync(0xffffffffu, l1, 1);
    l1 += __shfl_xor_sync(0xffffffffu, l1, 2);
    float i0 = 1.0f / l0, i1 = 1.0f / l1;

    float* op = g_ao + ((size_t)(bh >> 4) * NL + q0) * NC + h * ND;
    #pragma unroll
    for (int nt = 0; nt < 8; nt++) {
        int col = nt * 8 + 2 * tg;
        float2 r0v = make_float2(o[nt][0] * i0, o[nt][1] * i0);
        float2 r1v = make_float2(o[nt][2] * i1, o[nt][3] * i1);
        *(float2*)(op + (size_t)r0 * NC + col)       = r0v;
        *(float2*)(op + (size_t)(r0 + 8) * NC + col) = r1v;
    }
}

// ---------------- Kernel 4: output projection GEMM (TF32) + bias ------------
__global__ void __launch_bounds__(256)
k_proj(const float* __restrict__ w, const float* __restrict__ bp,
       float* __restrict__ out) {
    extern __shared__ unsigned smemu[];
    float acc[2][8][4];
    #pragma unroll
    for (int i = 0; i < 2; i++)
        #pragma unroll
        for (int j = 0; j < 8; j++)
            #pragma unroll
            for (int r = 0; r < 4; r++) acc[i][j][r] = 0.0f;

    const int n0 = blockIdx.x * 128;
    const int m0 = blockIdx.y * 128;
    gemm_tf32(g_ao, w, m0, n0, NC, smemu, acc);

    const int lane = threadIdx.x & 31, wid = threadIdx.x >> 5;
    const int wm = (wid & 3) << 5, wn = (wid >> 2) << 6;
    const int g = lane >> 2, tg = lane & 3;

    #pragma unroll
    for (int mt = 0; mt < 2; mt++) {
        #pragma unroll
        for (int half = 0; half < 2; half++) {
            int m = m0 + wm + mt * 16 + g + half * 8;
            #pragma unroll
            for (int nt = 0; nt < 8; nt++) {
                int n = n0 + wn + nt * 8 + 2 * tg;
                float2 b2 = *(const float2*)(bp + n);
                float2 r;
                r.x = acc[mt][nt][half * 2 + 0] + b2.x;
                r.y = acc[mt][nt][half * 2 + 1] + b2.y;
                *(float2*)(out + (size_t)m * NC + n) = r;
            }
        }
    }
}

// ---------------- host launcher ---------------------------------------------
extern "C" void kernel_launch(void* const* d_in, const int* in_sizes, int n_in,
                              void* d_out, int out_size) {
    const float* x         = (const float*)d_in[0];
    const float* attn_bias = (const float*)d_in[1];
    const float* w_qkv     = (const float*)d_in[2];
    const float* q_bias    = (const float*)d_in[3];
    const float* v_bias    = (const float*)d_in[4];
    const float* scale_mul = (const float*)d_in[5];
    const float* w_proj    = (const float*)d_in[6];
    const float* b_proj    = (const float*)d_in[7];
    float* out = (float*)d_out;

    const int GEMM_SMEM = 4 * SM_BUF * 4;   // 73728 B (double-buffered A+B)
    cudaFuncSetAttribute(k_qkv,  cudaFuncAttributeMaxDynamicSharedMemorySize, GEMM_SMEM);
    cudaFuncSetAttribute(k_proj, cudaFuncAttributeMaxDynamicSharedMemorySize, GEMM_SMEM);

    // QKV projection: [8192,1024] x [3072,1024]^T (TF32 tensor cores)
    k_qkv<<<dim3(24, 64), 256, GEMM_SMEM>>>(x, w_qkv, q_bias, v_bias);

    // L2-normalize q (with exp(min(scale,log100)) scale) and k
    k_norm<<<32768, 256>>>(scale_mul);

    // attention: bf16-split QK^T + tf32 PV flash attention, 64-row q tiles
    const int ATTN_SMEM = (2 * 64 * KP + 2 * 64 * AP) * 4;  // 53248 B
    cudaFuncSetAttribute(k_attn, cudaFuncAttributeMaxDynamicSharedMemorySize, ATTN_SMEM);
    k_attn<<<dim3(16, 128), 128, ATTN_SMEM>>>(attn_bias);

    // output projection: [8192,1024] x [1024,1024]^T (TF32 tensor cores)
    k_proj<<<dim3(8, 64), 256, GEMM_SMEM>>>(w_proj, b_proj, out);
}

// round 13
// speedup vs baseline: 1.3154x; 1.1040x over previous
#include <cuda_runtime.h>
#include <cuda_bf16.h>
#include <math.h>

// Problem constants
#define NB 8
#define NL 1024
#define NC 1024
#define NH 16
#define ND 64

// Scratch (device globals — no allocation allowed)
__device__ float g_q[NB*NH*NL*ND];   // [B,H,L,D]
__device__ float g_k[NB*NH*NL*ND];
__device__ float g_v[NB*NH*NL*ND];
__device__ float g_ao[NB*NL*NC];     // attention output, [B,L,C]

// ---------------- TF32 / BF16 tensor-core helpers ---------------------------
static __device__ __forceinline__ unsigned f2tf(float f) {
    unsigned r;
    asm("cvt.rna.tf32.f32 %0, %1;" : "=r"(r) : "f"(f));
    return r;
}
static __device__ __forceinline__ void mma_tf32(float c[4], const unsigned a[4],
                                                const unsigned b[2]) {
    asm("mma.sync.aligned.m16n8k8.row.col.f32.tf32.tf32.f32 "
        "{%0,%1,%2,%3}, {%4,%5,%6,%7}, {%8,%9}, {%0,%1,%2,%3};"
        : "+f"(c[0]), "+f"(c[1]), "+f"(c[2]), "+f"(c[3])
        : "r"(a[0]), "r"(a[1]), "r"(a[2]), "r"(a[3]), "r"(b[0]), "r"(b[1]));
}
static __device__ __forceinline__ void mma_bf16(float c[4], const unsigned a[4],
                                                const unsigned b[2]) {
    asm("mma.sync.aligned.m16n8k16.row.col.f32.bf16.bf16.f32 "
        "{%0,%1,%2,%3}, {%4,%5,%6,%7}, {%8,%9}, {%0,%1,%2,%3};"
        : "+f"(c[0]), "+f"(c[1]), "+f"(c[2]), "+f"(c[3])
        : "r"(a[0]), "r"(a[1]), "r"(a[2]), "r"(a[3]), "r"(b[0]), "r"(b[1]));
}
// pack two floats into bf16x2 (x -> low half, y -> high half)
static __device__ __forceinline__ unsigned pk_bf2(float x, float y) {
    unsigned r;
    asm("cvt.rn.bf16x2.f32 %0, %1, %2;" : "=r"(r) : "f"(y), "f"(x));
    return r;
}
static __device__ __forceinline__ float bf_res(float x) {
    __nv_bfloat16 h = __float2bfloat16(x);
    return x - __bfloat162float(h);
}
static __device__ __forceinline__ unsigned smem_u32(const void* p) {
    unsigned a;
    asm("{ .reg .u64 t; cvta.to.shared.u64 t, %1; cvt.u32.u64 %0, t; }"
        : "=r"(a) : "l"(p));
    return a;
}
// ldmatrix x4: four 8x8 b16 tiles; lane l supplies the 16B-row address of
// tile (l>>3), row (l&7).
static __device__ __forceinline__ void ldsm4(unsigned r[4], unsigned addr) {
    asm volatile("ldmatrix.sync.aligned.m8n8.x4.shared.b16 {%0,%1,%2,%3}, [%4];"
        : "=r"(r[0]), "=r"(r[1]), "=r"(r[2]), "=r"(r[3]) : "r"(addr));
}

// ---------------- TF32 NT GEMM core: 128x128 C-tile of A[M,K] * B[N,K]^T ----
// 256 threads = 8 warps arranged 4(M) x 2(N); warp tile 32x64.
// Fragments fetched with ldmatrix.x4 (pitch 36 -> conflict-free LDSM).
#define GPITCH 36
#define SM_BUF 4608                 // 128*36 words per tile buffer

__device__ __forceinline__ void gemm_tf32(const float* __restrict__ A,
                                          const float* __restrict__ Bw,
                                          int m0, int n0, int K,
                                          unsigned* sm, float acc[2][8][4]) {
    const int tid  = threadIdx.x;
    const int lane = tid & 31, wid = tid >> 5;
    const int wm = (wid & 3) << 5;           // warp m offset
    const int wn = (wid >> 2) << 6;          // warp n offset
    const int r0 = tid >> 3, slot = tid & 7; // loader: row base, float4 slot

    unsigned* sA[2] = { sm,              sm + SM_BUF };
    unsigned* sB[2] = { sm + 2 * SM_BUF, sm + 3 * SM_BUF };

    // ldmatrix lane-row addresses (bytes): lane l -> tile l>>3, row l&7
    const unsigned sbase = smem_u32(sm);
    const int l15 = lane & 15;                 // row within 16-row region
    const int lhi = (lane >> 4) * 16;          // 0 or 16 bytes (b32 col +4)
    const unsigned aR = sbase + (unsigned)((wm + l15) * GPITCH) * 4 + lhi;
    const unsigned bR = sbase + (unsigned)((2 * SM_BUF) + (wn + l15) * GPITCH) * 4 + lhi;

    const float* pA = A  + (size_t)(m0 + r0) * K + slot * 4;
    const float* pB = Bw + (size_t)(n0 + r0) * K + slot * 4;

    float4 a4[4], b4[4];
    // prologue: tile 0 -> buf 0
    #pragma unroll
    for (int i = 0; i < 4; i++) {
        a4[i] = *(const float4*)(pA + (size_t)(i * 32) * K);
        b4[i] = *(const float4*)(pB + (size_t)(i * 32) * K);
    }
    #pragma unroll
    for (int i = 0; i < 4; i++) {
        uint4 ua = make_uint4(f2tf(a4[i].x), f2tf(a4[i].y), f2tf(a4[i].z), f2tf(a4[i].w));
        uint4 ub = make_uint4(f2tf(b4[i].x), f2tf(b4[i].y), f2tf(b4[i].z), f2tf(b4[i].w));
        *(uint4*)(sA[0] + (r0 + i * 32) * GPITCH + slot * 4) = ua;
        *(uint4*)(sB[0] + (r0 + i * 32) * GPITCH + slot * 4) = ub;
    }
    __syncthreads();

    const int NT = K >> 5;                   // BK = 32
    for (int kt = 0; kt < NT; kt++) {
        const int cur = kt & 1;
        if (kt + 1 < NT) {
            const float* qA = pA + (kt + 1) * 32;
            const float* qB = pB + (kt + 1) * 32;
            #pragma unroll
            for (int i = 0; i < 4; i++) {
                a4[i] = *(const float4*)(qA + (size_t)(i * 32) * K);
                b4[i] = *(const float4*)(qB + (size_t)(i * 32) * K);
            }
        }
        const unsigned aCur = aR + (cur ? SM_BUF * 4u : 0u);
        const unsigned bCur = bR + (cur ? SM_BUF * 4u : 0u);
        #pragma unroll
        for (int ks = 0; ks < 4; ks++) {
            unsigned af[2][4];
            #pragma unroll
            for (int mt = 0; mt < 2; mt++)
                ldsm4(af[mt], aCur + (unsigned)(mt * 16 * GPITCH * 4) + ks * 32);
            #pragma unroll
            for (int ntp = 0; ntp < 4; ntp++) {
                unsigned bq[4];
                ldsm4(bq, bCur + (unsigned)(ntp * 16 * GPITCH * 4) + ks * 32);
                unsigned b0[2] = { bq[0], bq[2] };
                unsigned b1[2] = { bq[1], bq[3] };
                #pragma unroll
                for (int mt = 0; mt < 2; mt++) {
                    mma_tf32(acc[mt][2 * ntp],     af[mt], b0);
                    mma_tf32(acc[mt][2 * ntp + 1], af[mt], b1);
                }
            }
        }
        if (kt + 1 < NT) {
            const int nxt = cur ^ 1;
            #pragma unroll
            for (int i = 0; i < 4; i++) {
                uint4 ua = make_uint4(f2tf(a4[i].x), f2tf(a4[i].y), f2tf(a4[i].z), f2tf(a4[i].w));
                uint4 ub = make_uint4(f2tf(b4[i].x), f2tf(b4[i].y), f2tf(b4[i].z), f2tf(b4[i].w));
                *(uint4*)(sA[nxt] + (r0 + i * 32) * GPITCH + slot * 4) = ua;
                *(uint4*)(sB[nxt] + (r0 + i * 32) * GPITCH + slot * 4) = ub;
            }
        }
        __syncthreads();
    }
}

// ---------------- Kernel 1: QKV GEMM (TF32) + bias + scatter to [B,H,L,D] ---
__global__ void __launch_bounds__(256)
k_qkv(const float* __restrict__ x, const float* __restrict__ w,
      const float* __restrict__ qb, const float* __restrict__ vb) {
    extern __shared__ unsigned smemu[];
    float acc[2][8][4];
    #pragma unroll
    for (int i = 0; i < 2; i++)
        #pragma unroll
        for (int j = 0; j < 8; j++)
            #pragma unroll
            for (int r = 0; r < 4; r++) acc[i][j][r] = 0.0f;

    const int n0 = blockIdx.x * 128;
    const int m0 = blockIdx.y * 128;
    gemm_tf32(x, w, m0, n0, NC, smemu, acc);

    const int lane = threadIdx.x & 31, wid = threadIdx.x >> 5;
    const int wm = (wid & 3) << 5, wn = (wid >> 2) << 6;
    const int g = lane >> 2, tg = lane & 3;

    #pragma unroll
    for (int mt = 0; mt < 2; mt++) {
        #pragma unroll
        for (int half = 0; half < 2; half++) {
            int m  = m0 + wm + mt * 16 + g + half * 8;
            int bb = m >> 10;
            int l  = m & 1023;
            #pragma unroll
            for (int nt = 0; nt < 8; nt++) {
                int n     = n0 + wn + nt * 8 + 2 * tg;
                int which = n >> 10;           // 0=q 1=k 2=v
                int cc    = n & 1023;
                int h     = cc >> 6;
                int dd    = cc & 63;
                float2 r;
                r.x = acc[mt][nt][half * 2 + 0];
                r.y = acc[mt][nt][half * 2 + 1];
                float* dst;
                if (which == 0) {
                    float2 b2 = *(const float2*)(qb + cc);
                    r.x += b2.x; r.y += b2.y;
                    dst = g_q;
                } else if (which == 1) {
                    dst = g_k;
                } else {
                    float2 b2 = *(const float2*)(vb + cc);
                    r.x += b2.x; r.y += b2.y;
                    dst = g_v;
                }
                *(float2*)(dst + (((size_t)bb * NH + h) * NL + l) * ND + dd) = r;
            }
        }
    }
}

// ---------------- Kernel 2: per-(b,h,l) L2 normalize of q (scaled) and k ----
__global__ void k_norm(const float* __restrict__ scale_mul) {
    const int lane = threadIdx.x & 31;
    const int row  = blockIdx.x * (blockDim.x >> 5) + (threadIdx.x >> 5);
    const int NQ   = NB * NH * NL;
    const bool isq = row < NQ;
    const int r    = isq ? row : row - NQ;
    float* base = (isq ? g_q : g_k) + (size_t)r * ND;
    float2 v = ((float2*)base)[lane];
    float ss = v.x * v.x + v.y * v.y;
    #pragma unroll
    for (int m = 16; m >= 1; m >>= 1)
        ss += __shfl_xor_sync(0xffffffffu, ss, m);
    float mul = 1.0f;
    if (isq) {
        int h = (r >> 10) & 15;
        mul = __expf(fminf(scale_mul[h], 4.605170185988091f)); // log(100)
    }
    float sc = mul / fmaxf(sqrtf(ss), 1e-12f);
    v.x *= sc; v.y *= sc;
    ((float2*)base)[lane] = v;
}

// ---------------- Kernel 3: flash attention ---------------------------------
// QK^T: bf16 m16n8k16 hi/lo split (3 MMA per k16). PV: tf32 m16n8k8.
// All smem fragments via ldmatrix.x4. 4 warps x 16 q rows, 64-wide KV tiles.
#define KP 36                      // bf16x2 K-tile pitch (uints per row)
#define AP 68                      // tf32 V/P pitch (floats per row)

__global__ void __launch_bounds__(128)
k_attn(const float* __restrict__ bias) {
    extern __shared__ unsigned smu[];
    unsigned* Khs = smu;                     // [64][KP] bf16x2 hi(K)
    unsigned* Kls = smu + 64 * KP;           // [64][KP] bf16x2 lo(K)
    unsigned* Vt  = smu + 2 * 64 * KP;       // [64 d][AP] tf32(V) transposed
    unsigned* Ps  = smu + 2 * 64 * KP + 64 * AP;  // [64 rows][AP] tf32(P)

    const int t    = threadIdx.x;
    const int lane = t & 31, w = t >> 5;
    const int g = lane >> 2, tg = lane & 3;
    const int bh = blockIdx.y, h = bh & 15;
    const int q0 = blockIdx.x * 64;
    const int r0 = w * 16 + g;        // block-local q row (this thread: r0, r0+8)

    // ldmatrix lane addressing (bytes)
    const int l15 = lane & 15;
    const int lhi = (lane >> 4) * 16;
    const unsigned khR = smem_u32(Khs) + (unsigned)(l15 * KP) * 4 + lhi;
    const unsigned klR = smem_u32(Kls) + (unsigned)(l15 * KP) * 4 + lhi;
    const unsigned vtR = smem_u32(Vt)  + (unsigned)(l15 * AP) * 4 + lhi;
    const unsigned psR = smem_u32(Ps)  + (unsigned)((w * 16 + l15) * AP) * 4 + lhi;

    // Q fragments: bf16x2 hi/lo, m16n8k16 A-layout, resident all loop
    unsigned qh[4][4], ql[4][4];
    {
        const float* qbase = g_q + ((size_t)bh * NL + q0) * ND;
        #pragma unroll
        for (int kg = 0; kg < 4; kg++) {
            #pragma unroll
            for (int i = 0; i < 4; i++) {
                int row = r0 + (i & 1) * 8;
                int kk  = kg * 16 + 2 * tg + (i >> 1) * 8;
                float x0 = qbase[(size_t)row * ND + kk];
                float x1 = qbase[(size_t)row * ND + kk + 1];
                qh[kg][i] = pk_bf2(x0, x1);
                ql[kg][i] = pk_bf2(bf_res(x0), bf_res(x1));
            }
        }
    }

    float o[8][4];
    #pragma unroll
    for (int nt = 0; nt < 8; nt++)
        #pragma unroll
        for (int i = 0; i < 4; i++) o[nt][i] = 0.0f;
    float m0 = -INFINITY, m1 = -INFINITY, l0 = 0.0f, l1 = 0.0f;
    const float* bb = bias + (size_t)h * NL * NL;

    for (int j0 = 0; j0 < NL; j0 += 64) {
        __syncthreads();              // previous tile fully consumed
        // Load K tile (bf16x2 hi/lo) and V tile (transposed tf32)
        {
            const float* kp = g_k + ((size_t)bh * NL + j0) * ND;
            const float* vp = g_v + ((size_t)bh * NL + j0) * ND;
            #pragma unroll
            for (int it = 0; it < 8; it++) {
                int idx = t + it * 128;          // 1024 float4 slots
                int row = idx >> 4, c4 = (idx & 15) * 4;
                float4 k4 = *(const float4*)(kp + (size_t)row * ND + c4);
                float4 v4 = *(const float4*)(vp + (size_t)row * ND + c4);
                unsigned* kh = Khs + row * KP + (c4 >> 1);
                unsigned* kl = Kls + row * KP + (c4 >> 1);
                kh[0] = pk_bf2(k4.x, k4.y);
                kh[1] = pk_bf2(k4.z, k4.w);
                kl[0] = pk_bf2(bf_res(k4.x), bf_res(k4.y));
                kl[1] = pk_bf2(bf_res(k4.z), bf_res(k4.w));
                float vf[4] = {v4.x, v4.y, v4.z, v4.w};
                #pragma unroll
                for (int i = 0; i < 4; i++)
                    Vt[(c4 + i) * AP + row] = f2tf(vf[i]);
            }
        }
        __syncthreads();

        // S = Q K^T : bf16 k16, 3-term hi/lo split, ldmatrix B-frags
        float s[8][4];
        #pragma unroll
        for (int nt = 0; nt < 8; nt++)
            #pragma unroll
            for (int i = 0; i < 4; i++) s[nt][i] = 0.0f;
        #pragma unroll
        for (int kg = 0; kg < 4; kg++) {
            #pragma unroll
            for (int ntp = 0; ntp < 4; ntp++) {
                unsigned hb[4], lb[4];
                ldsm4(hb, khR + (unsigned)(ntp * 16 * KP + kg * 8) * 4);
                ldsm4(lb, klR + (unsigned)(ntp * 16 * KP + kg * 8) * 4);
                unsigned h0[2] = { hb[0], hb[2] }, h1[2] = { hb[1], hb[3] };
                unsigned e0[2] = { lb[0], lb[2] }, e1[2] = { lb[1], lb[3] };
                mma_bf16(s[2*ntp],     qh[kg], h0);
                mma_bf16(s[2*ntp],     ql[kg], h0);
                mma_bf16(s[2*ntp],     qh[kg], e0);
                mma_bf16(s[2*ntp + 1], qh[kg], h1);
                mma_bf16(s[2*ntp + 1], ql[kg], h1);
                mma_bf16(s[2*ntp + 1], qh[kg], e1);
            }
        }

        // bias add + tile max
        float tm0 = -INFINITY, tm1 = -INFINITY;
        #pragma unroll
        for (int nt = 0; nt < 8; nt++) {
            int col = j0 + nt * 8 + 2 * tg;
            float2 b0 = *(const float2*)(bb + (size_t)(q0 + r0) * NL + col);
            float2 b1 = *(const float2*)(bb + (size_t)(q0 + r0 + 8) * NL + col);
            s[nt][0] += b0.x; s[nt][1] += b0.y;
            s[nt][2] += b1.x; s[nt][3] += b1.y;
            tm0 = fmaxf(tm0, fmaxf(s[nt][0], s[nt][1]));
            tm1 = fmaxf(tm1, fmaxf(s[nt][2], s[nt][3]));
        }
        tm0 = fmaxf(tm0, __shfl_xor_sync(0xffffffffu, tm0, 1));
        tm0 = fmaxf(tm0, __shfl_xor_sync(0xffffffffu, tm0, 2));
        tm1 = fmaxf(tm1, __shfl_xor_sync(0xffffffffu, tm1, 1));
        tm1 = fmaxf(tm1, __shfl_xor_sync(0xffffffffu, tm1, 2));

        float mn0 = fmaxf(m0, tm0), mn1 = fmaxf(m1, tm1);
        float a0 = __expf(m0 - mn0), a1 = __expf(m1 - mn1);
        m0 = mn0; m1 = mn1;
        l0 *= a0; l1 *= a1;
        #pragma unroll
        for (int nt = 0; nt < 8; nt++) {
            o[nt][0] *= a0; o[nt][1] *= a0;
            o[nt][2] *= a1; o[nt][3] *= a1;
        }

        // p = exp(s - m); accumulate l; stage P into smem as tf32
        #pragma unroll
        for (int nt = 0; nt < 8; nt++) {
            float p0 = __expf(s[nt][0] - m0), p1 = __expf(s[nt][1] - m0);
            float p2 = __expf(s[nt][2] - m1), p3 = __expf(s[nt][3] - m1);
            l0 += p0 + p1; l1 += p2 + p3;
            unsigned* d0 = Ps + r0 * AP + nt * 8 + 2 * tg;
            unsigned* d1 = Ps + (r0 + 8) * AP + nt * 8 + 2 * tg;
            d0[0] = f2tf(p0); d0[1] = f2tf(p1);
            d1[0] = f2tf(p2); d1[1] = f2tf(p3);
        }
        __syncwarp();                  // Ps rows are warp-private

        // O += P V (tf32 k8), ldmatrix A- and B-frags
        #pragma unroll
        for (int kg = 0; kg < 8; kg++) {
            unsigned ap4[4];
            ldsm4(ap4, psR + (unsigned)(kg * 8) * 4);
            #pragma unroll
            for (int ntp = 0; ntp < 4; ntp++) {
                unsigned bv4[4];
                ldsm4(bv4, vtR + (unsigned)(ntp * 16 * AP + kg * 8) * 4);
                unsigned v0[2] = { bv4[0], bv4[2] }, v1[2] = { bv4[1], bv4[3] };
                mma_tf32(o[2*ntp],     ap4, v0);
                mma_tf32(o[2*ntp + 1], ap4, v1);
            }
        }
    }

    // finish l reduction across tg and write out
    l0 += __shfl_xor_sync(0xffffffffu, l0, 1);
    l0 += __shfl_xor_sync(0xffffffffu, l0, 2);
    l1 += __shfl_xor_sync(0xffffffffu, l1, 1);
    l1 += __shfl_xor_sync(0xffffffffu, l1, 2);
    float i0 = 1.0f / l0, i1 = 1.0f / l1;

    float* op = g_ao + ((size_t)(bh >> 4) * NL + q0) * NC + h * ND;
    #pragma unroll
    for (int nt = 0; nt < 8; nt++) {
        int col = nt * 8 + 2 * tg;
        float2 r0v = make_float2(o[nt][0] * i0, o[nt][1] * i0);
        float2 r1v = make_float2(o[nt][2] * i1, o[nt][3] * i1);
        *(float2*)(op + (size_t)r0 * NC + col)       = r0v;
        *(float2*)(op + (size_t)(r0 + 8) * NC + col) = r1v;
    }
}

// ---------------- Kernel 4: output projection GEMM (TF32) + bias ------------
__global__ void __launch_bounds__(256)
k_proj(const float* __restrict__ w, const float* __restrict__ bp,
       float* __restrict__ out) {
    extern __shared__ unsigned smemu[];
    float acc[2][8][4];
    #pragma unroll
    for (int i = 0; i < 2; i++)
        #pragma unroll
        for (int j = 0; j < 8; j++)
            #pragma unroll
            for (int r = 0; r < 4; r++) acc[i][j][r] = 0.0f;

    const int n0 = blockIdx.x * 128;
    const int m0 = blockIdx.y * 128;
    gemm_tf32(g_ao, w, m0, n0, NC, smemu, acc);

    const int lane = threadIdx.x & 31, wid = threadIdx.x >> 5;
    const int wm = (wid & 3) << 5, wn = (wid >> 2) << 6;
    const int g = lane >> 2, tg = lane & 3;

    #pragma unroll
    for (int mt = 0; mt < 2; mt++) {
        #pragma unroll
        for (int half = 0; half < 2; half++) {
            int m = m0 + wm + mt * 16 + g + half * 8;
            #pragma unroll
            for (int nt = 0; nt < 8; nt++) {
                int n = n0 + wn + nt * 8 + 2 * tg;
                float2 b2 = *(const float2*)(bp + n);
                float2 r;
                r.x = acc[mt][nt][half * 2 + 0] + b2.x;
                r.y = acc[mt][nt][half * 2 + 1] + b2.y;
                *(float2*)(out + (size_t)m * NC + n) = r;
            }
        }
    }
}

// ---------------- host launcher ---------------------------------------------
extern "C" void kernel_launch(void* const* d_in, const int* in_sizes, int n_in,
                              void* d_out, int out_size) {
    const float* x         = (const float*)d_in[0];
    const float* attn_bias = (const float*)d_in[1];
    const float* w_qkv     = (const float*)d_in[2];
    const float* q_bias    = (const float*)d_in[3];
    const float* v_bias    = (const float*)d_in[4];
    const float* scale_mul = (const float*)d_in[5];
    const float* w_proj    = (const float*)d_in[6];
    const float* b_proj    = (const float*)d_in[7];
    float* out = (float*)d_out;

    const int GEMM_SMEM = 4 * SM_BUF * 4;   // 73728 B (double-buffered A+B)
    cudaFuncSetAttribute(k_qkv,  cudaFuncAttributeMaxDynamicSharedMemorySize, GEMM_SMEM);
    cudaFuncSetAttribute(k_proj, cudaFuncAttributeMaxDynamicSharedMemorySize, GEMM_SMEM);

    // QKV projection: [8192,1024] x [3072,1024]^T (TF32 tensor cores)
    k_qkv<<<dim3(24, 64), 256, GEMM_SMEM>>>(x, w_qkv, q_bias, v_bias);

    // L2-normalize q (with exp(min(scale,log100)) scale) and k
    k_norm<<<32768, 256>>>(scale_mul);

    // attention: bf16-split QK^T + tf32 PV flash attention, 64-row q tiles
    const int ATTN_SMEM = (2 * 64 * KP + 2 * 64 * AP) * 4;  // 53248 B
    cudaFuncSetAttribute(k_attn, cudaFuncAttributeMaxDynamicSharedMemorySize, ATTN_SMEM);
    k_attn<<<dim3(16, 128), 128, ATTN_SMEM>>>(attn_bias);

    // output projection: [8192,1024] x [1024,1024]^T (TF32 tensor cores)
    k_proj<<<dim3(8, 64), 256, GEMM_SMEM>>>(w_proj, b_proj, out);
}

// round 14
// speedup vs baseline: 1.5171x; 1.1533x over previous
#include <cuda_runtime.h>
#include <cuda_bf16.h>
#include <math.h>

// Problem constants
#define NB 8
#define NL 1024
#define NC 1024
#define NH 16
#define ND 64

// Scratch (device globals — no allocation allowed)
__device__ float g_q[NB*NH*NL*ND];   // [B,H,L,D]
__device__ float g_k[NB*NH*NL*ND];
__device__ float g_v[NB*NH*NL*ND];
__device__ __align__(16) unsigned g_xtf[NB*NL*NC];     // tf32(x)
__device__ __align__(16) unsigned g_wqkv_tf[3*NC*NC];  // tf32(w_qkv)
__device__ __align__(16) unsigned g_wproj_tf[NC*NC];   // tf32(w_proj)
__device__ __align__(16) unsigned g_aotf[NB*NL*NC];    // tf32(attn out) [B,L,C]

// ---------------- scalar/PTX helpers ----------------------------------------
static __device__ __forceinline__ unsigned f2tf(float f) {
    unsigned r;
    asm("cvt.rna.tf32.f32 %0, %1;" : "=r"(r) : "f"(f));
    return r;
}
static __device__ __forceinline__ void mma_tf32(float c[4], const unsigned a[4],
                                                const unsigned b[2]) {
    asm("mma.sync.aligned.m16n8k8.row.col.f32.tf32.tf32.f32 "
        "{%0,%1,%2,%3}, {%4,%5,%6,%7}, {%8,%9}, {%0,%1,%2,%3};"
        : "+f"(c[0]), "+f"(c[1]), "+f"(c[2]), "+f"(c[3])
        : "r"(a[0]), "r"(a[1]), "r"(a[2]), "r"(a[3]), "r"(b[0]), "r"(b[1]));
}
static __device__ __forceinline__ void mma_bf16(float c[4], const unsigned a[4],
                                                const unsigned b[2]) {
    asm("mma.sync.aligned.m16n8k16.row.col.f32.bf16.bf16.f32 "
        "{%0,%1,%2,%3}, {%4,%5,%6,%7}, {%8,%9}, {%0,%1,%2,%3};"
        : "+f"(c[0]), "+f"(c[1]), "+f"(c[2]), "+f"(c[3])
        : "r"(a[0]), "r"(a[1]), "r"(a[2]), "r"(a[3]), "r"(b[0]), "r"(b[1]));
}
static __device__ __forceinline__ void mma_fp16(float c[4], const unsigned a[4],
                                                const unsigned b[2]) {
    asm("mma.sync.aligned.m16n8k16.row.col.f32.f16.f16.f32 "
        "{%0,%1,%2,%3}, {%4,%5,%6,%7}, {%8,%9}, {%0,%1,%2,%3};"
        : "+f"(c[0]), "+f"(c[1]), "+f"(c[2]), "+f"(c[3])
        : "r"(a[0]), "r"(a[1]), "r"(a[2]), "r"(a[3]), "r"(b[0]), "r"(b[1]));
}
// pack two floats (x -> low half, y -> high half)
static __device__ __forceinline__ unsigned pk_bf2(float x, float y) {
    unsigned r;
    asm("cvt.rn.bf16x2.f32 %0, %1, %2;" : "=r"(r) : "f"(y), "f"(x));
    return r;
}
static __device__ __forceinline__ unsigned pk_f16(float x, float y) {
    unsigned r;
    asm("cvt.rn.f16x2.f32 %0, %1, %2;" : "=r"(r) : "f"(y), "f"(x));
    return r;
}
static __device__ __forceinline__ float bf_res(float x) {
    __nv_bfloat16 h = __float2bfloat16(x);
    return x - __bfloat162float(h);
}
static __device__ __forceinline__ unsigned smem_u32(const void* p) {
    unsigned a;
    asm("{ .reg .u64 t; cvta.to.shared.u64 t, %1; cvt.u32.u64 %0, t; }"
        : "=r"(a) : "l"(p));
    return a;
}
static __device__ __forceinline__ void ldsm4(unsigned r[4], unsigned addr) {
    asm volatile("ldmatrix.sync.aligned.m8n8.x4.shared.b16 {%0,%1,%2,%3}, [%4];"
        : "=r"(r[0]), "=r"(r[1]), "=r"(r[2]), "=r"(r[3]) : "r"(addr));
}
static __device__ __forceinline__ void cpa16(unsigned dst, const void* src) {
    asm volatile("cp.async.cg.shared.global [%0], [%1], 16;"
                 :: "r"(dst), "l"(src) : "memory");
}
static __device__ __forceinline__ void cpa_commit() {
    asm volatile("cp.async.commit_group;" ::: "memory");
}
static __device__ __forceinline__ void cpa_wait1() {
    asm volatile("cp.async.wait_group 1;" ::: "memory");
}

// ---------------- Prep: tf32 pre-conversion of x, w_qkv, w_proj -------------
__global__ void __launch_bounds__(256)
k_cvt3(const float4* __restrict__ x, const float4* __restrict__ wq,
       const float4* __restrict__ wp) {
    int i = blockIdx.x * blockDim.x + threadIdx.x;
    const int NX = NB*NL*NC/4;          // 2097152
    const int NW = 3*NC*NC/4;           // 786432
    const int NP = NC*NC/4;             // 262144
    float4 v; uint4* d;
    if (i < NX)                { v = x[i];            d = (uint4*)g_xtf + i; }
    else if (i < NX + NW)      { v = wq[i - NX];      d = (uint4*)g_wqkv_tf + (i - NX); }
    else if (i < NX + NW + NP) { v = wp[i - NX - NW]; d = (uint4*)g_wproj_tf + (i - NX - NW); }
    else return;
    *d = make_uint4(f2tf(v.x), f2tf(v.y), f2tf(v.z), f2tf(v.w));
}

// ---------------- TF32 NT GEMM, cp.async 3-stage: C[128x128] = A B^T --------
// Pre-converted tf32 inputs. 256 threads = 8 warps (4M x 2N), warp tile 32x64.
// Pitch 36 words: conflict-free LDSM and 16B-aligned cp.async rows.
#define GP 36
#define STGW (128*GP)               // 4608 words per operand per stage
#define GEMM_SMEM (3 * 2 * STGW * 4)   // 110592 B

__device__ __forceinline__ void gemm_tf32(const unsigned* __restrict__ A,
                                          const unsigned* __restrict__ Bw,
                                          int m0, int n0, int K,
                                          unsigned* sm, float acc[2][8][4]) {
    const int tid  = threadIdx.x;
    const int lane = tid & 31, wid = tid >> 5;
    const int wm = (wid & 3) << 5;
    const int wn = (wid >> 2) << 6;
    const int r0 = tid >> 3, slot = tid & 7;

    const unsigned sbase = smem_u32(sm);
    const int l15 = lane & 15;
    const int lhi = (lane >> 4) * 16;
    const unsigned aR = sbase + (unsigned)((wm + l15) * GP) * 4 + lhi;
    const unsigned bR = sbase + (unsigned)(STGW + (wn + l15) * GP) * 4 + lhi;

    const unsigned* pA = A  + (size_t)(m0 + r0) * K + slot * 4;
    const unsigned* pB = Bw + (size_t)(n0 + r0) * K + slot * 4;
    const unsigned aDst = sbase + (unsigned)(r0 * GP + slot * 4) * 4;
    const unsigned bDst = aDst + STGW * 4;

    const int NT = K >> 5;                  // BK = 32

    // prologue: stages 0,1
    #pragma unroll
    for (int s = 0; s < 2; s++) {
        const unsigned off = s * (2 * STGW * 4);
        #pragma unroll
        for (int i = 0; i < 4; i++) {
            cpa16(aDst + off + i * (32 * GP * 4), pA + (size_t)i * 32 * K + s * 32);
            cpa16(bDst + off + i * (32 * GP * 4), pB + (size_t)i * 32 * K + s * 32);
        }
        cpa_commit();
    }

    int buf_w = 2;                          // next write buffer
    for (int kt = 0; kt < NT; kt++) {
        cpa_wait1();                        // stage kt resident
        __syncthreads();                    // all warps done with stage kt-1
        if (kt + 2 < NT) {
            const unsigned off = buf_w * (2 * STGW * 4);
            #pragma unroll
            for (int i = 0; i < 4; i++) {
                cpa16(aDst + off + i * (32 * GP * 4),
                      pA + (size_t)i * 32 * K + (kt + 2) * 32);
                cpa16(bDst + off + i * (32 * GP * 4),
                      pB + (size_t)i * 32 * K + (kt + 2) * 32);
            }
        }
        cpa_commit();                       // always (group counting)
        if (++buf_w == 3) buf_w = 0;

        const unsigned boff = (unsigned)(kt % 3) * (2 * STGW * 4);
        #pragma unroll
        for (int ks = 0; ks < 4; ks++) {
            unsigned af[2][4];
            ldsm4(af[0], aR + boff + ks * 32);
            ldsm4(af[1], aR + boff + (16 * GP * 4) + ks * 32);
            #pragma unroll
            for (int ntp = 0; ntp < 4; ntp++) {
                unsigned bq[4];
                ldsm4(bq, bR + boff + (unsigned)(ntp * 16 * GP * 4) + ks * 32);
                unsigned b0[2] = { bq[0], bq[2] };
                unsigned b1[2] = { bq[1], bq[3] };
                #pragma unroll
                for (int mt = 0; mt < 2; mt++) {
                    mma_tf32(acc[mt][2 * ntp],     af[mt], b0);
                    mma_tf32(acc[mt][2 * ntp + 1], af[mt], b1);
                }
            }
        }
    }
}

// ---------------- Kernel 1: QKV GEMM + bias + scatter to [B,H,L,D] ----------
__global__ void __launch_bounds__(256)
k_qkv(const float* __restrict__ qb, const float* __restrict__ vb) {
    extern __shared__ unsigned smemu[];
    float acc[2][8][4];
    #pragma unroll
    for (int i = 0; i < 2; i++)
        #pragma unroll
        for (int j = 0; j < 8; j++)
            #pragma unroll
            for (int r = 0; r < 4; r++) acc[i][j][r] = 0.0f;

    const int n0 = blockIdx.x * 128;
    const int m0 = blockIdx.y * 128;
    gemm_tf32(g_xtf, g_wqkv_tf, m0, n0, NC, smemu, acc);

    const int lane = threadIdx.x & 31, wid = threadIdx.x >> 5;
    const int wm = (wid & 3) << 5, wn = (wid >> 2) << 6;
    const int g = lane >> 2, tg = lane & 3;

    #pragma unroll
    for (int mt = 0; mt < 2; mt++) {
        #pragma unroll
        for (int half = 0; half < 2; half++) {
            int m  = m0 + wm + mt * 16 + g + half * 8;
            int bb = m >> 10;
            int l  = m & 1023;
            #pragma unroll
            for (int nt = 0; nt < 8; nt++) {
                int n     = n0 + wn + nt * 8 + 2 * tg;
                int which = n >> 10;           // 0=q 1=k 2=v
                int cc    = n & 1023;
                int h     = cc >> 6;
                int dd    = cc & 63;
                float2 r;
                r.x = acc[mt][nt][half * 2 + 0];
                r.y = acc[mt][nt][half * 2 + 1];
                float* dst;
                if (which == 0) {
                    float2 b2 = *(const float2*)(qb + cc);
                    r.x += b2.x; r.y += b2.y;
                    dst = g_q;
                } else if (which == 1) {
                    dst = g_k;
                } else {
                    float2 b2 = *(const float2*)(vb + cc);
                    r.x += b2.x; r.y += b2.y;
                    dst = g_v;
                }
                *(float2*)(dst + (((size_t)bb * NH + h) * NL + l) * ND + dd) = r;
            }
        }
    }
}

// ---------------- Kernel 2: per-(b,h,l) L2 normalize of q (scaled) and k ----
__global__ void k_norm(const float* __restrict__ scale_mul) {
    const int lane = threadIdx.x & 31;
    const int row  = blockIdx.x * (blockDim.x >> 5) + (threadIdx.x >> 5);
    const int NQ   = NB * NH * NL;
    const bool isq = row < NQ;
    const int r    = isq ? row : row - NQ;
    float* base = (isq ? g_q : g_k) + (size_t)r * ND;
    float2 v = ((float2*)base)[lane];
    float ss = v.x * v.x + v.y * v.y;
    #pragma unroll
    for (int m = 16; m >= 1; m >>= 1)
        ss += __shfl_xor_sync(0xffffffffu, ss, m);
    float mul = 1.0f;
    if (isq) {
        int h = (r >> 10) & 15;
        mul = __expf(fminf(scale_mul[h], 4.605170185988091f)); // log(100)
    }
    float sc = mul / fmaxf(sqrtf(ss), 1e-12f);
    v.x *= sc; v.y *= sc;
    ((float2*)base)[lane] = v;
}

// ---------------- Kernel 3: flash attention ---------------------------------
// QK^T: bf16 m16n8k16 hi/lo split (3 MMA per k16).
// PV:   fp16 m16n8k16 single (same 10-bit mantissa as tf32, half the MMAs).
// All fragments via ldmatrix.x4; epilogue emits tf32 bits for the proj GEMM.
#define KP 36                      // bf16x2 K-tile pitch (uints per row)
#define VP 36                      // f16x2 V/P pitch (uints per row)

__global__ void __launch_bounds__(128)
k_attn(const float* __restrict__ bias) {
    extern __shared__ unsigned smu[];
    unsigned* Khs = smu;                      // [64][KP] bf16x2 hi(K)
    unsigned* Kls = smu + 64 * KP;            // [64][KP] bf16x2 lo(K)
    unsigned* Vh  = smu + 2 * 64 * KP;        // [64 d][VP] f16x2(V^T), kv pairs
    unsigned* Ps  = smu + 2 * 64 * KP + 64 * VP;  // [64 q][VP] f16x2(P)

    const int t    = threadIdx.x;
    const int lane = t & 31, w = t >> 5;
    const int g = lane >> 2, tg = lane & 3;
    const int bh = blockIdx.y, h = bh & 15;
    const int q0 = blockIdx.x * 64;
    const int r0 = w * 16 + g;        // block-local q row (this thread: r0, r0+8)

    // ldmatrix lane addressing (bytes)
    const int l15 = lane & 15;
    const int lhi = (lane >> 4) * 16;
    const unsigned khR = smem_u32(Khs) + (unsigned)(l15 * KP) * 4 + lhi;
    const unsigned klR = smem_u32(Kls) + (unsigned)(l15 * KP) * 4 + lhi;
    const unsigned vhR = smem_u32(Vh)  + (unsigned)(l15 * VP) * 4 + lhi;
    const unsigned psR = smem_u32(Ps)  + (unsigned)((w * 16 + l15) * VP) * 4 + lhi;

    // Q fragments: bf16x2 hi/lo, m16n8k16 A-layout, resident all loop
    unsigned qh[4][4], ql[4][4];
    {
        const float* qbase = g_q + ((size_t)bh * NL + q0) * ND;
        #pragma unroll
        for (int kg = 0; kg < 4; kg++) {
            #pragma unroll
            for (int i = 0; i < 4; i++) {
                int row = r0 + (i & 1) * 8;
                int kk  = kg * 16 + 2 * tg + (i >> 1) * 8;
                float x0 = qbase[(size_t)row * ND + kk];
                float x1 = qbase[(size_t)row * ND + kk + 1];
                qh[kg][i] = pk_bf2(x0, x1);
                ql[kg][i] = pk_bf2(bf_res(x0), bf_res(x1));
            }
        }
    }

    float o[8][4];
    #pragma unroll
    for (int nt = 0; nt < 8; nt++)
        #pragma unroll
        for (int i = 0; i < 4; i++) o[nt][i] = 0.0f;
    float m0 = -INFINITY, m1 = -INFINITY, l0 = 0.0f, l1 = 0.0f;
    const float* bb = bias + (size_t)h * NL * NL;

    for (int j0 = 0; j0 < NL; j0 += 64) {
        __syncthreads();              // previous tile fully consumed
        {
            const float* kp = g_k + ((size_t)bh * NL + j0) * ND;
            const float* vp = g_v + ((size_t)bh * NL + j0) * ND;
            // K tile: 64 rows x 16 float4, bf16x2 hi/lo
            #pragma unroll
            for (int it = 0; it < 8; it++) {
                int idx = t + it * 128;
                int row = idx >> 4, c4 = (idx & 15) * 4;
                float4 k4 = *(const float4*)(kp + (size_t)row * ND + c4);
                unsigned* kh = Khs + row * KP + (c4 >> 1);
                unsigned* kl = Kls + row * KP + (c4 >> 1);
                kh[0] = pk_bf2(k4.x, k4.y);
                kh[1] = pk_bf2(k4.z, k4.w);
                kl[0] = pk_bf2(bf_res(k4.x), bf_res(k4.y));
                kl[1] = pk_bf2(bf_res(k4.z), bf_res(k4.w));
            }
            // V tile: 32 kv-pairs x 16 float4-cols, transposed f16x2 pack
            #pragma unroll
            for (int it = 0; it < 4; it++) {
                int idx = t + it * 128;           // 512 tasks
                int p = idx >> 4, c4 = (idx & 15) * 4;
                float4 va = *(const float4*)(vp + (size_t)(2 * p) * ND + c4);
                float4 vb2 = *(const float4*)(vp + (size_t)(2 * p + 1) * ND + c4);
                float fa[4] = {va.x, va.y, va.z, va.w};
                float fb[4] = {vb2.x, vb2.y, vb2.z, vb2.w};
                #pragma unroll
                for (int i = 0; i < 4; i++)
                    Vh[(c4 + i) * VP + p] = pk_f16(fa[i], fb[i]);
            }
        }
        __syncthreads();

        // S = Q K^T : bf16 k16, 3-term hi/lo split
        float s[8][4];
        #pragma unroll
        for (int nt = 0; nt < 8; nt++)
            #pragma unroll
            for (int i = 0; i < 4; i++) s[nt][i] = 0.0f;
        #pragma unroll
        for (int kg = 0; kg < 4; kg++) {
            #pragma unroll
            for (int ntp = 0; ntp < 4; ntp++) {
                unsigned hb[4], lb[4];
                ldsm4(hb, khR + (unsigned)(ntp * 16 * KP + kg * 8) * 4);
                ldsm4(lb, klR + (unsigned)(ntp * 16 * KP + kg * 8) * 4);
                unsigned h0[2] = { hb[0], hb[2] }, h1[2] = { hb[1], hb[3] };
                unsigned e0[2] = { lb[0], lb[2] }, e1[2] = { lb[1], lb[3] };
                mma_bf16(s[2*ntp],     qh[kg], h0);
                mma_bf16(s[2*ntp],     ql[kg], h0);
                mma_bf16(s[2*ntp],     qh[kg], e0);
                mma_bf16(s[2*ntp + 1], qh[kg], h1);
                mma_bf16(s[2*ntp + 1], ql[kg], h1);
                mma_bf16(s[2*ntp + 1], qh[kg], e1);
            }
        }

        // bias add + tile max
        float tm0 = -INFINITY, tm1 = -INFINITY;
        #pragma unroll
        for (int nt = 0; nt < 8; nt++) {
            int col = j0 + nt * 8 + 2 * tg;
            float2 b0 = *(const float2*)(bb + (size_t)(q0 + r0) * NL + col);
            float2 b1 = *(const float2*)(bb + (size_t)(q0 + r0 + 8) * NL + col);
            s[nt][0] += b0.x; s[nt][1] += b0.y;
            s[nt][2] += b1.x; s[nt][3] += b1.y;
            tm0 = fmaxf(tm0, fmaxf(s[nt][0], s[nt][1]));
            tm1 = fmaxf(tm1, fmaxf(s[nt][2], s[nt][3]));
        }
        tm0 = fmaxf(tm0, __shfl_xor_sync(0xffffffffu, tm0, 1));
        tm0 = fmaxf(tm0, __shfl_xor_sync(0xffffffffu, tm0, 2));
        tm1 = fmaxf(tm1, __shfl_xor_sync(0xffffffffu, tm1, 1));
        tm1 = fmaxf(tm1, __shfl_xor_sync(0xffffffffu, tm1, 2));

        float mn0 = fmaxf(m0, tm0), mn1 = fmaxf(m1, tm1);
        float a0 = __expf(m0 - mn0), a1 = __expf(m1 - mn1);
        m0 = mn0; m1 = mn1;
        l0 *= a0; l1 *= a1;
        #pragma unroll
        for (int nt = 0; nt < 8; nt++) {
            o[nt][0] *= a0; o[nt][1] *= a0;
            o[nt][2] *= a1; o[nt][3] *= a1;
        }

        // p = exp(s - m); accumulate l; stage P into smem as f16x2
        #pragma unroll
        for (int nt = 0; nt < 8; nt++) {
            float p0 = __expf(s[nt][0] - m0), p1 = __expf(s[nt][1] - m0);
            float p2 = __expf(s[nt][2] - m1), p3 = __expf(s[nt][3] - m1);
            l0 += p0 + p1; l1 += p2 + p3;
            Ps[r0 * VP + nt * 4 + tg]       = pk_f16(p0, p1);
            Ps[(r0 + 8) * VP + nt * 4 + tg] = pk_f16(p2, p3);
        }
        __syncwarp();                  // Ps rows are warp-private

        // O += P V (fp16 k16)
        #pragma unroll
        for (int kg = 0; kg < 4; kg++) {
            unsigned ap4[4];
            ldsm4(ap4, psR + (unsigned)(kg * 32));
            #pragma unroll
            for (int ntp = 0; ntp < 4; ntp++) {
                unsigned bv4[4];
                ldsm4(bv4, vhR + (unsigned)(ntp * 16 * VP * 4) + kg * 32);
                unsigned v0[2] = { bv4[0], bv4[2] }, v1[2] = { bv4[1], bv4[3] };
                mma_fp16(o[2*ntp],     ap4, v0);
                mma_fp16(o[2*ntp + 1], ap4, v1);
            }
        }
    }

    // finish l reduction across tg and write out as tf32 bits (proj A operand)
    l0 += __shfl_xor_sync(0xffffffffu, l0, 1);
    l0 += __shfl_xor_sync(0xffffffffu, l0, 2);
    l1 += __shfl_xor_sync(0xffffffffu, l1, 1);
    l1 += __shfl_xor_sync(0xffffffffu, l1, 2);
    float i0 = 1.0f / l0, i1 = 1.0f / l1;

    unsigned* op = g_aotf + ((size_t)(bh >> 4) * NL + q0) * NC + h * ND;
    #pragma unroll
    for (int nt = 0; nt < 8; nt++) {
        int col = nt * 8 + 2 * tg;
        uint2 r0v = make_uint2(f2tf(o[nt][0] * i0), f2tf(o[nt][1] * i0));
        uint2 r1v = make_uint2(f2tf(o[nt][2] * i1), f2tf(o[nt][3] * i1));
        *(uint2*)(op + (size_t)r0 * NC + col)       = r0v;
        *(uint2*)(op + (size_t)(r0 + 8) * NC + col) = r1v;
    }
}

// ---------------- Kernel 4: output projection GEMM + bias -------------------
__global__ void __launch_bounds__(256)
k_proj(const float* __restrict__ bp, float* __restrict__ out) {
    extern __shared__ unsigned smemu[];
    float acc[2][8][4];
    #pragma unroll
    for (int i = 0; i < 2; i++)
        #pragma unroll
        for (int j = 0; j < 8; j++)
            #pragma unroll
            for (int r = 0; r < 4; r++) acc[i][j][r] = 0.0f;

    const int n0 = blockIdx.x * 128;
    const int m0 = blockIdx.y * 128;
    gemm_tf32(g_aotf, g_wproj_tf, m0, n0, NC, smemu, acc);

    const int lane = threadIdx.x & 31, wid = threadIdx.x >> 5;
    const int wm = (wid & 3) << 5, wn = (wid >> 2) << 6;
    const int g = lane >> 2, tg = lane & 3;

    #pragma unroll
    for (int mt = 0; mt < 2; mt++) {
        #pragma unroll
        for (int half = 0; half < 2; half++) {
            int m = m0 + wm + mt * 16 + g + half * 8;
            #pragma unroll
            for (int nt = 0; nt < 8; nt++) {
                int n = n0 + wn + nt * 8 + 2 * tg;
                float2 b2 = *(const float2*)(bp + n);
                float2 r;
                r.x = acc[mt][nt][half * 2 + 0] + b2.x;
                r.y = acc[mt][nt][half * 2 + 1] + b2.y;
                *(float2*)(out + (size_t)m * NC + n) = r;
            }
        }
    }
}

// ---------------- host launcher ---------------------------------------------
extern "C" void kernel_launch(void* const* d_in, const int* in_sizes, int n_in,
                              void* d_out, int out_size) {
    const float* x         = (const float*)d_in[0];
    const float* attn_bias = (const float*)d_in[1];
    const float* w_qkv     = (const float*)d_in[2];
    const float* q_bias    = (const float*)d_in[3];
    const float* v_bias    = (const float*)d_in[4];
    const float* scale_mul = (const float*)d_in[5];
    const float* w_proj    = (const float*)d_in[6];
    const float* b_proj    = (const float*)d_in[7];
    float* out = (float*)d_out;

    cudaFuncSetAttribute(k_qkv,  cudaFuncAttributeMaxDynamicSharedMemorySize, GEMM_SMEM);
    cudaFuncSetAttribute(k_proj, cudaFuncAttributeMaxDynamicSharedMemorySize, GEMM_SMEM);

    // tf32 pre-conversion of x, w_qkv, w_proj (feeds cp.async GEMMs)
    k_cvt3<<<12288, 256>>>((const float4*)x, (const float4*)w_qkv,
                           (const float4*)w_proj);

    // QKV projection: [8192,1024] x [3072,1024]^T, cp.async 3-stage TF32
    k_qkv<<<dim3(24, 64), 256, GEMM_SMEM>>>(q_bias, v_bias);

    // L2-normalize q (with exp(min(scale,log100)) scale) and k
    k_norm<<<32768, 256>>>(scale_mul);

    // attention: bf16-split QK^T + fp16 PV flash attention, 64-row q tiles
    const int ATTN_SMEM = (2 * 64 * KP + 2 * 64 * VP) * 4;  // 36864 B
    cudaFuncSetAttribute(k_attn, cudaFuncAttributeMaxDynamicSharedMemorySize, ATTN_SMEM);
    k_attn<<<dim3(16, 128), 128, ATTN_SMEM>>>(attn_bias);

    // output projection: [8192,1024] x [1024,1024]^T, cp.async 3-stage TF32
    k_proj<<<dim3(8, 64), 256, GEMM_SMEM>>>(b_proj, out);
}

// round 15
// speedup vs baseline: 1.5667x; 1.0327x over previous
#include <cuda_runtime.h>
#include <cuda_bf16.h>
#include <cuda_fp16.h>
#include <math.h>

// Problem constants
#define NB 8
#define NL 1024
#define NC 1024
#define NH 16
#define ND 64

// Scratch (device globals — no allocation allowed)
__device__ float g_q[NB*NH*NL*ND];   // [B,H,L,D]
__device__ float g_k[NB*NH*NL*ND];
__device__ float g_v[NB*NH*NL*ND];
__device__ __align__(16) unsigned g_xtf[NB*NL*NC];     // tf32(x)
__device__ __align__(16) unsigned g_wqkv_tf[3*NC*NC];  // tf32(w_qkv)
__device__ __align__(16) unsigned g_wproj_tf[NC*NC];   // tf32(w_proj)
__device__ __align__(16) unsigned g_aotf[NB*NL*NC];    // tf32(attn out) [B,L,C]

// ---------------- scalar/PTX helpers ----------------------------------------
static __device__ __forceinline__ unsigned f2tf(float f) {
    unsigned r;
    asm("cvt.rna.tf32.f32 %0, %1;" : "=r"(r) : "f"(f));
    return r;
}
static __device__ __forceinline__ void mma_tf32(float c[4], const unsigned a[4],
                                                const unsigned b[2]) {
    asm("mma.sync.aligned.m16n8k8.row.col.f32.tf32.tf32.f32 "
        "{%0,%1,%2,%3}, {%4,%5,%6,%7}, {%8,%9}, {%0,%1,%2,%3};"
        : "+f"(c[0]), "+f"(c[1]), "+f"(c[2]), "+f"(c[3])
        : "r"(a[0]), "r"(a[1]), "r"(a[2]), "r"(a[3]), "r"(b[0]), "r"(b[1]));
}
static __device__ __forceinline__ void mma_fp16(float c[4], const unsigned a[4],
                                                const unsigned b[2]) {
    asm("mma.sync.aligned.m16n8k16.row.col.f32.f16.f16.f32 "
        "{%0,%1,%2,%3}, {%4,%5,%6,%7}, {%8,%9}, {%0,%1,%2,%3};"
        : "+f"(c[0]), "+f"(c[1]), "+f"(c[2]), "+f"(c[3])
        : "r"(a[0]), "r"(a[1]), "r"(a[2]), "r"(a[3]), "r"(b[0]), "r"(b[1]));
}
// pack two floats (x -> low half, y -> high half)
static __device__ __forceinline__ unsigned pk_f16(float x, float y) {
    unsigned r;
    asm("cvt.rn.f16x2.f32 %0, %1, %2;" : "=r"(r) : "f"(y), "f"(x));
    return r;
}
static __device__ __forceinline__ float f16_res(float x) {
    __half h = __float2half(x);
    return x - __half2float(h);
}
static __device__ __forceinline__ unsigned smem_u32(const void* p) {
    unsigned a;
    asm("{ .reg .u64 t; cvta.to.shared.u64 t, %1; cvt.u32.u64 %0, t; }"
        : "=r"(a) : "l"(p));
    return a;
}
static __device__ __forceinline__ void ldsm4(unsigned r[4], unsigned addr) {
    asm volatile("ldmatrix.sync.aligned.m8n8.x4.shared.b16 {%0,%1,%2,%3}, [%4];"
        : "=r"(r[0]), "=r"(r[1]), "=r"(r[2]), "=r"(r[3]) : "r"(addr));
}
static __device__ __forceinline__ void cpa16(unsigned dst, const void* src) {
    asm volatile("cp.async.cg.shared.global [%0], [%1], 16;"
                 :: "r"(dst), "l"(src) : "memory");
}
static __device__ __forceinline__ void cpa_commit() {
    asm volatile("cp.async.commit_group;" ::: "memory");
}
static __device__ __forceinline__ void cpa_wait1() {
    asm volatile("cp.async.wait_group 1;" ::: "memory");
}

// ---------------- Prep: tf32 pre-conversion of x, w_qkv, w_proj -------------
__global__ void __launch_bounds__(256)
k_cvt3(const float4* __restrict__ x, const float4* __restrict__ wq,
       const float4* __restrict__ wp) {
    int i = blockIdx.x * blockDim.x + threadIdx.x;
    const int NX = NB*NL*NC/4;          // 2097152
    const int NW = 3*NC*NC/4;           // 786432
    const int NP = NC*NC/4;             // 262144
    float4 v; uint4* d;
    if (i < NX)                { v = x[i];            d = (uint4*)g_xtf + i; }
    else if (i < NX + NW)      { v = wq[i - NX];      d = (uint4*)g_wqkv_tf + (i - NX); }
    else if (i < NX + NW + NP) { v = wp[i - NX - NW]; d = (uint4*)g_wproj_tf + (i - NX - NW); }
    else return;
    *d = make_uint4(f2tf(v.x), f2tf(v.y), f2tf(v.z), f2tf(v.w));
}

// ---------------- TF32 NT GEMM, cp.async 3-stage: C[128x128] = A B^T --------
// Pre-converted tf32 inputs. 256 threads = 8 warps (4M x 2N), warp tile 32x64.
// Pitch 36 words: conflict-free LDSM and 16B-aligned cp.async rows.
#define GP 36
#define STGW (128*GP)               // 4608 words per operand per stage
#define GEMM_SMEM (3 * 2 * STGW * 4)   // 110592 B

__device__ __forceinline__ void gemm_tf32(const unsigned* __restrict__ A,
                                          const unsigned* __restrict__ Bw,
                                          int m0, int n0, int K,
                                          unsigned* sm, float acc[2][8][4]) {
    const int tid  = threadIdx.x;
    const int lane = tid & 31, wid = tid >> 5;
    const int wm = (wid & 3) << 5;
    const int wn = (wid >> 2) << 6;
    const int r0 = tid >> 3, slot = tid & 7;

    const unsigned sbase = smem_u32(sm);
    const int l15 = lane & 15;
    const int lhi = (lane >> 4) * 16;
    const unsigned aR = sbase + (unsigned)((wm + l15) * GP) * 4 + lhi;
    const unsigned bR = sbase + (unsigned)(STGW + (wn + l15) * GP) * 4 + lhi;

    const unsigned* pA = A  + (size_t)(m0 + r0) * K + slot * 4;
    const unsigned* pB = Bw + (size_t)(n0 + r0) * K + slot * 4;
    const unsigned aDst = sbase + (unsigned)(r0 * GP + slot * 4) * 4;
    const unsigned bDst = aDst + STGW * 4;

    const int NT = K >> 5;                  // BK = 32

    // prologue: stages 0,1
    #pragma unroll
    for (int s = 0; s < 2; s++) {
        const unsigned off = s * (2 * STGW * 4);
        #pragma unroll
        for (int i = 0; i < 4; i++) {
            cpa16(aDst + off + i * (32 * GP * 4), pA + (size_t)i * 32 * K + s * 32);
            cpa16(bDst + off + i * (32 * GP * 4), pB + (size_t)i * 32 * K + s * 32);
        }
        cpa_commit();
    }

    int buf_w = 2;                          // next write buffer
    for (int kt = 0; kt < NT; kt++) {
        cpa_wait1();                        // stage kt resident
        __syncthreads();                    // all warps done with stage kt-1
        if (kt + 2 < NT) {
            const unsigned off = buf_w * (2 * STGW * 4);
            #pragma unroll
            for (int i = 0; i < 4; i++) {
                cpa16(aDst + off + i * (32 * GP * 4),
                      pA + (size_t)i * 32 * K + (kt + 2) * 32);
                cpa16(bDst + off + i * (32 * GP * 4),
                      pB + (size_t)i * 32 * K + (kt + 2) * 32);
            }
        }
        cpa_commit();                       // always (group counting)
        if (++buf_w == 3) buf_w = 0;

        const unsigned boff = (unsigned)(kt % 3) * (2 * STGW * 4);
        #pragma unroll
        for (int ks = 0; ks < 4; ks++) {
            unsigned af[2][4];
            ldsm4(af[0], aR + boff + ks * 32);
            ldsm4(af[1], aR + boff + (16 * GP * 4) + ks * 32);
            #pragma unroll
            for (int ntp = 0; ntp < 4; ntp++) {
                unsigned bq[4];
                ldsm4(bq, bR + boff + (unsigned)(ntp * 16 * GP * 4) + ks * 32);
                unsigned b0[2] = { bq[0], bq[2] };
                unsigned b1[2] = { bq[1], bq[3] };
                #pragma unroll
                for (int mt = 0; mt < 2; mt++) {
                    mma_tf32(acc[mt][2 * ntp],     af[mt], b0);
                    mma_tf32(acc[mt][2 * ntp + 1], af[mt], b1);
                }
            }
        }
    }
}

// ---------------- Kernel 1: QKV GEMM + bias + scatter to [B,H,L,D] ----------
__global__ void __launch_bounds__(256)
k_qkv(const float* __restrict__ qb, const float* __restrict__ vb) {
    extern __shared__ unsigned smemu[];
    float acc[2][8][4];
    #pragma unroll
    for (int i = 0; i < 2; i++)
        #pragma unroll
        for (int j = 0; j < 8; j++)
            #pragma unroll
            for (int r = 0; r < 4; r++) acc[i][j][r] = 0.0f;

    const int n0 = blockIdx.x * 128;
    const int m0 = blockIdx.y * 128;
    gemm_tf32(g_xtf, g_wqkv_tf, m0, n0, NC, smemu, acc);

    const int lane = threadIdx.x & 31, wid = threadIdx.x >> 5;
    const int wm = (wid & 3) << 5, wn = (wid >> 2) << 6;
    const int g = lane >> 2, tg = lane & 3;

    #pragma unroll
    for (int mt = 0; mt < 2; mt++) {
        #pragma unroll
        for (int half = 0; half < 2; half++) {
            int m  = m0 + wm + mt * 16 + g + half * 8;
            int bb = m >> 10;
            int l  = m & 1023;
            #pragma unroll
            for (int nt = 0; nt < 8; nt++) {
                int n     = n0 + wn + nt * 8 + 2 * tg;
                int which = n >> 10;           // 0=q 1=k 2=v
                int cc    = n & 1023;
                int h     = cc >> 6;
                int dd    = cc & 63;
                float2 r;
                r.x = acc[mt][nt][half * 2 + 0];
                r.y = acc[mt][nt][half * 2 + 1];
                float* dst;
                if (which == 0) {
                    float2 b2 = *(const float2*)(qb + cc);
                    r.x += b2.x; r.y += b2.y;
                    dst = g_q;
                } else if (which == 1) {
                    dst = g_k;
                } else {
                    float2 b2 = *(const float2*)(vb + cc);
                    r.x += b2.x; r.y += b2.y;
                    dst = g_v;
                }
                *(float2*)(dst + (((size_t)bb * NH + h) * NL + l) * ND + dd) = r;
            }
        }
    }
}

// ---------------- Kernel 2: per-(b,h,l) L2 normalize of q (scaled) and k ----
__global__ void k_norm(const float* __restrict__ scale_mul) {
    const int lane = threadIdx.x & 31;
    const int row  = blockIdx.x * (blockDim.x >> 5) + (threadIdx.x >> 5);
    const int NQ   = NB * NH * NL;
    const bool isq = row < NQ;
    const int r    = isq ? row : row - NQ;
    float* base = (isq ? g_q : g_k) + (size_t)r * ND;
    float2 v = ((float2*)base)[lane];
    float ss = v.x * v.x + v.y * v.y;
    #pragma unroll
    for (int m = 16; m >= 1; m >>= 1)
        ss += __shfl_xor_sync(0xffffffffu, ss, m);
    float mul = 1.0f;
    if (isq) {
        int h = (r >> 10) & 15;
        mul = __expf(fminf(scale_mul[h], 4.605170185988091f)); // log(100)
    }
    float sc = mul / fmaxf(sqrtf(ss), 1e-12f);
    v.x *= sc; v.y *= sc;
    ((float2*)base)[lane] = v;
}

// ---------------- Kernel 3: flash attention ---------------------------------
// QK^T: fp16 m16n8k16, asymmetric split S = Qh.K + Ql.K (single fp16 K copy —
// halves K smem bytes/LDSM vs the bf16 symmetric split; K-rounding error
// ~2.8e-4 absolute on S, inside budget).
// PV:   fp16 m16n8k16 single. All fragments via ldmatrix.x4.
#define KP 36                      // f16x2 K-tile pitch (uints per row)
#define VP 36                      // f16x2 V/P pitch (uints per row)

__global__ void __launch_bounds__(128)
k_attn(const float* __restrict__ bias) {
    extern __shared__ unsigned smu[];
    unsigned* Kf = smu;                      // [64][KP] f16x2(K), k pairs
    unsigned* Vh = smu + 64 * KP;            // [64 d][VP] f16x2(V^T), kv pairs
    unsigned* Ps = smu + 64 * KP + 64 * VP;  // [64 q][VP] f16x2(P)

    const int t    = threadIdx.x;
    const int lane = t & 31, w = t >> 5;
    const int g = lane >> 2, tg = lane & 3;
    const int bh = blockIdx.y, h = bh & 15;
    const int q0 = blockIdx.x * 64;
    const int r0 = w * 16 + g;        // block-local q row (this thread: r0, r0+8)

    // ldmatrix lane addressing (bytes)
    const int l15 = lane & 15;
    const int lhi = (lane >> 4) * 16;
    const unsigned kfR = smem_u32(Kf) + (unsigned)(l15 * KP) * 4 + lhi;
    const unsigned vhR = smem_u32(Vh) + (unsigned)(l15 * VP) * 4 + lhi;
    const unsigned psR = smem_u32(Ps) + (unsigned)((w * 16 + l15) * VP) * 4 + lhi;

    // Q fragments: f16x2 hi/lo (Qh + Ql reconstructs fp32 q to ~2^-22)
    unsigned qh[4][4], ql[4][4];
    {
        const float* qbase = g_q + ((size_t)bh * NL + q0) * ND;
        #pragma unroll
        for (int kg = 0; kg < 4; kg++) {
            #pragma unroll
            for (int i = 0; i < 4; i++) {
                int row = r0 + (i & 1) * 8;
                int kk  = kg * 16 + 2 * tg + (i >> 1) * 8;
                float x0 = qbase[(size_t)row * ND + kk];
                float x1 = qbase[(size_t)row * ND + kk + 1];
                qh[kg][i] = pk_f16(x0, x1);
                ql[kg][i] = pk_f16(f16_res(x0), f16_res(x1));
            }
        }
    }

    float o[8][4];
    #pragma unroll
    for (int nt = 0; nt < 8; nt++)
        #pragma unroll
        for (int i = 0; i < 4; i++) o[nt][i] = 0.0f;
    float m0 = -INFINITY, m1 = -INFINITY, l0 = 0.0f, l1 = 0.0f;
    const float* bb = bias + (size_t)h * NL * NL;

    for (int j0 = 0; j0 < NL; j0 += 64) {
        __syncthreads();              // previous tile fully consumed
        {
            const float* kp = g_k + ((size_t)bh * NL + j0) * ND;
            const float* vp = g_v + ((size_t)bh * NL + j0) * ND;
            // K tile: 64 rows x 16 float4 -> single f16x2 copy
            #pragma unroll
            for (int it = 0; it < 8; it++) {
                int idx = t + it * 128;
                int row = idx >> 4, c4 = (idx & 15) * 4;
                float4 k4 = *(const float4*)(kp + (size_t)row * ND + c4);
                unsigned* kf = Kf + row * KP + (c4 >> 1);
                kf[0] = pk_f16(k4.x, k4.y);
                kf[1] = pk_f16(k4.z, k4.w);
            }
            // V tile: 32 kv-pairs x 16 float4-cols, transposed f16x2 pack
            #pragma unroll
            for (int it = 0; it < 4; it++) {
                int idx = t + it * 128;           // 512 tasks
                int p = idx >> 4, c4 = (idx & 15) * 4;
                float4 va = *(const float4*)(vp + (size_t)(2 * p) * ND + c4);
                float4 vb2 = *(const float4*)(vp + (size_t)(2 * p + 1) * ND + c4);
                float fa[4] = {va.x, va.y, va.z, va.w};
                float fb[4] = {vb2.x, vb2.y, vb2.z, vb2.w};
                #pragma unroll
                for (int i = 0; i < 4; i++)
                    Vh[(c4 + i) * VP + p] = pk_f16(fa[i], fb[i]);
            }
        }
        __syncthreads();

        // S = Q K^T : fp16 k16, 2-term asymmetric split
        float s[8][4];
        #pragma unroll
        for (int nt = 0; nt < 8; nt++)
            #pragma unroll
            for (int i = 0; i < 4; i++) s[nt][i] = 0.0f;
        #pragma unroll
        for (int kg = 0; kg < 4; kg++) {
            #pragma unroll
            for (int ntp = 0; ntp < 4; ntp++) {
                unsigned hb[4];
                ldsm4(hb, kfR + (unsigned)(ntp * 16 * KP + kg * 8) * 4);
                unsigned h0[2] = { hb[0], hb[2] }, h1[2] = { hb[1], hb[3] };
                mma_fp16(s[2*ntp],     qh[kg], h0);
                mma_fp16(s[2*ntp],     ql[kg], h0);
                mma_fp16(s[2*ntp + 1], qh[kg], h1);
                mma_fp16(s[2*ntp + 1], ql[kg], h1);
            }
        }

        // bias add + tile max
        float tm0 = -INFINITY, tm1 = -INFINITY;
        #pragma unroll
        for (int nt = 0; nt < 8; nt++) {
            int col = j0 + nt * 8 + 2 * tg;
            float2 b0 = *(const float2*)(bb + (size_t)(q0 + r0) * NL + col);
            float2 b1 = *(const float2*)(bb + (size_t)(q0 + r0 + 8) * NL + col);
            s[nt][0] += b0.x; s[nt][1] += b0.y;
            s[nt][2] += b1.x; s[nt][3] += b1.y;
            tm0 = fmaxf(tm0, fmaxf(s[nt][0], s[nt][1]));
            tm1 = fmaxf(tm1, fmaxf(s[nt][2], s[nt][3]));
        }
        tm0 = fmaxf(tm0, __shfl_xor_sync(0xffffffffu, tm0, 1));
        tm0 = fmaxf(tm0, __shfl_xor_sync(0xffffffffu, tm0, 2));
        tm1 = fmaxf(tm1, __shfl_xor_sync(0xffffffffu, tm1, 1));
        tm1 = fmaxf(tm1, __shfl_xor_sync(0xffffffffu, tm1, 2));

        float mn0 = fmaxf(m0, tm0), mn1 = fmaxf(m1, tm1);
        float a0 = __expf(m0 - mn0), a1 = __expf(m1 - mn1);
        m0 = mn0; m1 = mn1;
        l0 *= a0; l1 *= a1;
        #pragma unroll
        for (int nt = 0; nt < 8; nt++) {
            o[nt][0] *= a0; o[nt][1] *= a0;
            o[nt][2] *= a1; o[nt][3] *= a1;
        }

        // p = exp(s - m); accumulate l; stage P into smem as f16x2
        #pragma unroll
        for (int nt = 0; nt < 8; nt++) {
            float p0 = __expf(s[nt][0] - m0), p1 = __expf(s[nt][1] - m0);
            float p2 = __expf(s[nt][2] - m1), p3 = __expf(s[nt][3] - m1);
            l0 += p0 + p1; l1 += p2 + p3;
            Ps[r0 * VP + nt * 4 + tg]       = pk_f16(p0, p1);
            Ps[(r0 + 8) * VP + nt * 4 + tg] = pk_f16(p2, p3);
        }
        __syncwarp();                  // Ps rows are warp-private

        // O += P V (fp16 k16)
        #pragma unroll
        for (int kg = 0; kg < 4; kg++) {
            unsigned ap4[4];
            ldsm4(ap4, psR + (unsigned)(kg * 32));
            #pragma unroll
            for (int ntp = 0; ntp < 4; ntp++) {
                unsigned bv4[4];
                ldsm4(bv4, vhR + (unsigned)(ntp * 16 * VP * 4) + kg * 32);
                unsigned v0[2] = { bv4[0], bv4[2] }, v1[2] = { bv4[1], bv4[3] };
                mma_fp16(o[2*ntp],     ap4, v0);
                mma_fp16(o[2*ntp + 1], ap4, v1);
            }
        }
    }

    // finish l reduction across tg and write out as tf32 bits (proj A operand)
    l0 += __shfl_xor_sync(0xffffffffu, l0, 1);
    l0 += __shfl_xor_sync(0xffffffffu, l0, 2);
    l1 += __shfl_xor_sync(0xffffffffu, l1, 1);
    l1 += __shfl_xor_sync(0xffffffffu, l1, 2);
    float i0 = 1.0f / l0, i1 = 1.0f / l1;

    unsigned* op = g_aotf + ((size_t)(bh >> 4) * NL + q0) * NC + h * ND;
    #pragma unroll
    for (int nt = 0; nt < 8; nt++) {
        int col = nt * 8 + 2 * tg;
        uint2 r0v = make_uint2(f2tf(o[nt][0] * i0), f2tf(o[nt][1] * i0));
        uint2 r1v = make_uint2(f2tf(o[nt][2] * i1), f2tf(o[nt][3] * i1));
        *(uint2*)(op + (size_t)r0 * NC + col)       = r0v;
        *(uint2*)(op + (size_t)(r0 + 8) * NC + col) = r1v;
    }
}

// ---------------- Kernel 4: output projection GEMM + bias -------------------
__global__ void __launch_bounds__(256)
k_proj(const float* __restrict__ bp, float* __restrict__ out) {
    extern __shared__ unsigned smemu[];
    float acc[2][8][4];
    #pragma unroll
    for (int i = 0; i < 2; i++)
        #pragma unroll
        for (int j = 0; j < 8; j++)
            #pragma unroll
            for (int r = 0; r < 4; r++) acc[i][j][r] = 0.0f;

    const int n0 = blockIdx.x * 128;
    const int m0 = blockIdx.y * 128;
    gemm_tf32(g_aotf, g_wproj_tf, m0, n0, NC, smemu, acc);

    const int lane = threadIdx.x & 31, wid = threadIdx.x >> 5;
    const int wm = (wid & 3) << 5, wn = (wid >> 2) << 6;
    const int g = lane >> 2, tg = lane & 3;

    #pragma unroll
    for (int mt = 0; mt < 2; mt++) {
        #pragma unroll
        for (int half = 0; half < 2; half++) {
            int m = m0 + wm + mt * 16 + g + half * 8;
            #pragma unroll
            for (int nt = 0; nt < 8; nt++) {
                int n = n0 + wn + nt * 8 + 2 * tg;
                float2 b2 = *(const float2*)(bp + n);
                float2 r;
                r.x = acc[mt][nt][half * 2 + 0] + b2.x;
                r.y = acc[mt][nt][half * 2 + 1] + b2.y;
                *(float2*)(out + (size_t)m * NC + n) = r;
            }
        }
    }
}

// ---------------- host launcher ---------------------------------------------
extern "C" void kernel_launch(void* const* d_in, const int* in_sizes, int n_in,
                              void* d_out, int out_size) {
    const float* x         = (const float*)d_in[0];
    const float* attn_bias = (const float*)d_in[1];
    const float* w_qkv     = (const float*)d_in[2];
    const float* q_bias    = (const float*)d_in[3];
    const float* v_bias    = (const float*)d_in[4];
    const float* scale_mul = (const float*)d_in[5];
    const float* w_proj    = (const float*)d_in[6];
    const float* b_proj    = (const float*)d_in[7];
    float* out = (float*)d_out;

    cudaFuncSetAttribute(k_qkv,  cudaFuncAttributeMaxDynamicSharedMemorySize, GEMM_SMEM);
    cudaFuncSetAttribute(k_proj, cudaFuncAttributeMaxDynamicSharedMemorySize, GEMM_SMEM);

    // tf32 pre-conversion of x, w_qkv, w_proj (feeds cp.async GEMMs)
    k_cvt3<<<12288, 256>>>((const float4*)x, (const float4*)w_qkv,
                           (const float4*)w_proj);

    // QKV projection: [8192,1024] x [3072,1024]^T, cp.async 3-stage TF32
    k_qkv<<<dim3(24, 64), 256, GEMM_SMEM>>>(q_bias, v_bias);

    // L2-normalize q (with exp(min(scale,log100)) scale) and k
    k_norm<<<32768, 256>>>(scale_mul);

    // attention: fp16 asymmetric-split QK^T + fp16 PV, 64-row q tiles
    const int ATTN_SMEM = (64 * KP + 2 * 64 * VP) * 4;  // 27648 B
    cudaFuncSetAttribute(k_attn, cudaFuncAttributeMaxDynamicSharedMemorySize, ATTN_SMEM);
    k_attn<<<dim3(16, 128), 128, ATTN_SMEM>>>(attn_bias);

    // output projection: [8192,1024] x [1024,1024]^T, cp.async 3-stage TF32
    k_proj<<<dim3(8, 64), 256, GEMM_SMEM>>>(b_proj, out);
}

// round 16
// speedup vs baseline: 1.8283x; 1.1670x over previous
#include <cuda_runtime.h>
#include <cuda_bf16.h>
#include <cuda_fp16.h>
#include <math.h>

// Problem constants
#define NB 8
#define NL 1024
#define NC 1024
#define NH 16
#define ND 64

// Scratch (device globals — no allocation allowed)
__device__ float g_q[NB*NH*NL*ND];   // [B,H,L,D]
__device__ float g_k[NB*NH*NL*ND];
__device__ float g_v[NB*NH*NL*ND];
__device__ __align__(16) unsigned g_xtf[NB*NL*NC];     // tf32(x)
__device__ __align__(16) unsigned g_wqkv_tf[3*NC*NC];  // tf32(w_qkv)
__device__ __align__(16) unsigned g_wproj_tf[NC*NC];   // tf32(w_proj)
__device__ __align__(16) unsigned g_aotf[NB*NL*NC];    // tf32(attn out) [B,L,C]
__device__ __align__(16) unsigned g_kf16[NB*NH*NL*ND/2]; // f16x2(K), [bh][l][d/2]
__device__ __align__(16) unsigned g_vt16[NB*NH*ND*NL/2]; // f16x2(V^T), [bh][d][l/2]

// ---------------- scalar/PTX helpers ----------------------------------------
static __device__ __forceinline__ unsigned f2tf(float f) {
    unsigned r;
    asm("cvt.rna.tf32.f32 %0, %1;" : "=r"(r) : "f"(f));
    return r;
}
static __device__ __forceinline__ void mma_tf32(float c[4], const unsigned a[4],
                                                const unsigned b[2]) {
    asm("mma.sync.aligned.m16n8k8.row.col.f32.tf32.tf32.f32 "
        "{%0,%1,%2,%3}, {%4,%5,%6,%7}, {%8,%9}, {%0,%1,%2,%3};"
        : "+f"(c[0]), "+f"(c[1]), "+f"(c[2]), "+f"(c[3])
        : "r"(a[0]), "r"(a[1]), "r"(a[2]), "r"(a[3]), "r"(b[0]), "r"(b[1]));
}
static __device__ __forceinline__ void mma_fp16(float c[4], const unsigned a[4],
                                                const unsigned b[2]) {
    asm("mma.sync.aligned.m16n8k16.row.col.f32.f16.f16.f32 "
        "{%0,%1,%2,%3}, {%4,%5,%6,%7}, {%8,%9}, {%0,%1,%2,%3};"
        : "+f"(c[0]), "+f"(c[1]), "+f"(c[2]), "+f"(c[3])
        : "r"(a[0]), "r"(a[1]), "r"(a[2]), "r"(a[3]), "r"(b[0]), "r"(b[1]));
}
// pack two floats (x -> low half, y -> high half)
static __device__ __forceinline__ unsigned pk_f16(float x, float y) {
    unsigned r;
    asm("cvt.rn.f16x2.f32 %0, %1, %2;" : "=r"(r) : "f"(y), "f"(x));
    return r;
}
static __device__ __forceinline__ float f16_res(float x) {
    __half h = __float2half(x);
    return x - __half2float(h);
}
static __device__ __forceinline__ unsigned smem_u32(const void* p) {
    unsigned a;
    asm("{ .reg .u64 t; cvta.to.shared.u64 t, %1; cvt.u32.u64 %0, t; }"
        : "=r"(a) : "l"(p));
    return a;
}
static __device__ __forceinline__ void ldsm4(unsigned r[4], unsigned addr) {
    asm volatile("ldmatrix.sync.aligned.m8n8.x4.shared.b16 {%0,%1,%2,%3}, [%4];"
        : "=r"(r[0]), "=r"(r[1]), "=r"(r[2]), "=r"(r[3]) : "r"(addr));
}
static __device__ __forceinline__ void cpa16(unsigned dst, const void* src) {
    asm volatile("cp.async.cg.shared.global [%0], [%1], 16;"
                 :: "r"(dst), "l"(src) : "memory");
}
static __device__ __forceinline__ void cpa_commit() {
    asm volatile("cp.async.commit_group;" ::: "memory");
}
static __device__ __forceinline__ void cpa_wait0() {
    asm volatile("cp.async.wait_group 0;" ::: "memory");
}
static __device__ __forceinline__ void cpa_wait1() {
    asm volatile("cp.async.wait_group 1;" ::: "memory");
}

// ---------------- Prep: tf32 pre-conversion of x, w_qkv, w_proj -------------
__global__ void __launch_bounds__(256)
k_cvt3(const float4* __restrict__ x, const float4* __restrict__ wq,
       const float4* __restrict__ wp) {
    int i = blockIdx.x * blockDim.x + threadIdx.x;
    const int NX = NB*NL*NC/4;          // 2097152
    const int NW = 3*NC*NC/4;           // 786432
    const int NP = NC*NC/4;             // 262144
    float4 v; uint4* d;
    if (i < NX)                { v = x[i];            d = (uint4*)g_xtf + i; }
    else if (i < NX + NW)      { v = wq[i - NX];      d = (uint4*)g_wqkv_tf + (i - NX); }
    else if (i < NX + NW + NP) { v = wp[i - NX - NW]; d = (uint4*)g_wproj_tf + (i - NX - NW); }
    else return;
    *d = make_uint4(f2tf(v.x), f2tf(v.y), f2tf(v.z), f2tf(v.w));
}

// ---------------- Prep: K -> f16x2 (linear), V -> f16x2 transposed ----------
__global__ void __launch_bounds__(256)
k_prep_k16() {
    int i = blockIdx.x * 256 + threadIdx.x;     // float4 index, 2097152 total
    float4 v = ((const float4*)g_k)[i];
    g_kf16[2*i]     = pk_f16(v.x, v.y);
    g_kf16[2*i + 1] = pk_f16(v.z, v.w);
}
__global__ void __launch_bounds__(256)
k_prep_vt() {
    __shared__ float sm[64 * 65];
    const int bh = blockIdx.x >> 4;
    const int l0 = (blockIdx.x & 15) * 64;
    const int t = threadIdx.x;
    const float* vp = g_v + (size_t)bh * NL * ND + (size_t)l0 * ND;
    #pragma unroll
    for (int i = 0; i < 4; i++) {
        int idx = t + i * 256;          // 1024 float4: [64 l][16 f4]
        int l = idx >> 4, d4 = (idx & 15) * 4;
        float4 f = *(const float4*)(vp + (size_t)l * ND + d4);
        float* s = sm + l * 65 + d4;
        s[0] = f.x; s[1] = f.y; s[2] = f.z; s[3] = f.w;
    }
    __syncthreads();
    unsigned* out = g_vt16 + (size_t)bh * (ND * NL / 2) + (l0 >> 1);
    #pragma unroll
    for (int i = 0; i < 8; i++) {
        int idx = t + i * 256;          // 2048 u32: [64 d][32 p]
        int d = idx >> 5, p = idx & 31;
        out[(size_t)d * (NL / 2) + p] =
            pk_f16(sm[(2 * p) * 65 + d], sm[(2 * p + 1) * 65 + d]);
    }
}

// ---------------- TF32 NT GEMM, cp.async 3-stage: C[128x128] = A B^T --------
// Pre-converted tf32 inputs. 256 threads = 8 warps (4M x 2N), warp tile 32x64.
// Pitch 36 words: conflict-free LDSM and 16B-aligned cp.async rows.
#define GP 36
#define STGW (128*GP)               // 4608 words per operand per stage
#define GEMM_SMEM (3 * 2 * STGW * 4)   // 110592 B

__device__ __forceinline__ void gemm_tf32(const unsigned* __restrict__ A,
                                          const unsigned* __restrict__ Bw,
                                          int m0, int n0, int K,
                                          unsigned* sm, float acc[2][8][4]) {
    const int tid  = threadIdx.x;
    const int lane = tid & 31, wid = tid >> 5;
    const int wm = (wid & 3) << 5;
    const int wn = (wid >> 2) << 6;
    const int r0 = tid >> 3, slot = tid & 7;

    const unsigned sbase = smem_u32(sm);
    const int l15 = lane & 15;
    const int lhi = (lane >> 4) * 16;
    const unsigned aR = sbase + (unsigned)((wm + l15) * GP) * 4 + lhi;
    const unsigned bR = sbase + (unsigned)(STGW + (wn + l15) * GP) * 4 + lhi;

    const unsigned* pA = A  + (size_t)(m0 + r0) * K + slot * 4;
    const unsigned* pB = Bw + (size_t)(n0 + r0) * K + slot * 4;
    const unsigned aDst = sbase + (unsigned)(r0 * GP + slot * 4) * 4;
    const unsigned bDst = aDst + STGW * 4;

    const int NT = K >> 5;                  // BK = 32

    // prologue: stages 0,1
    #pragma unroll
    for (int s = 0; s < 2; s++) {
        const unsigned off = s * (2 * STGW * 4);
        #pragma unroll
        for (int i = 0; i < 4; i++) {
            cpa16(aDst + off + i * (32 * GP * 4), pA + (size_t)i * 32 * K + s * 32);
            cpa16(bDst + off + i * (32 * GP * 4), pB + (size_t)i * 32 * K + s * 32);
        }
        cpa_commit();
    }

    int buf_w = 2;                          // next write buffer
    for (int kt = 0; kt < NT; kt++) {
        cpa_wait1();                        // stage kt resident
        __syncthreads();                    // all warps done with stage kt-1
        if (kt + 2 < NT) {
            const unsigned off = buf_w * (2 * STGW * 4);
            #pragma unroll
            for (int i = 0; i < 4; i++) {
                cpa16(aDst + off + i * (32 * GP * 4),
                      pA + (size_t)i * 32 * K + (kt + 2) * 32);
                cpa16(bDst + off + i * (32 * GP * 4),
                      pB + (size_t)i * 32 * K + (kt + 2) * 32);
            }
        }
        cpa_commit();                       // always (group counting)
        if (++buf_w == 3) buf_w = 0;

        const unsigned boff = (unsigned)(kt % 3) * (2 * STGW * 4);
        #pragma unroll
        for (int ks = 0; ks < 4; ks++) {
            unsigned af[2][4];
            ldsm4(af[0], aR + boff + ks * 32);
            ldsm4(af[1], aR + boff + (16 * GP * 4) + ks * 32);
            #pragma unroll
            for (int ntp = 0; ntp < 4; ntp++) {
                unsigned bq[4];
                ldsm4(bq, bR + boff + (unsigned)(ntp * 16 * GP * 4) + ks * 32);
                unsigned b0[2] = { bq[0], bq[2] };
                unsigned b1[2] = { bq[1], bq[3] };
                #pragma unroll
                for (int mt = 0; mt < 2; mt++) {
                    mma_tf32(acc[mt][2 * ntp],     af[mt], b0);
                    mma_tf32(acc[mt][2 * ntp + 1], af[mt], b1);
                }
            }
        }
    }
}

// ---------------- Kernel 1: QKV GEMM + bias + scatter to [B,H,L,D] ----------
__global__ void __launch_bounds__(256)
k_qkv(const float* __restrict__ qb, const float* __restrict__ vb) {
    extern __shared__ unsigned smemu[];
    float acc[2][8][4];
    #pragma unroll
    for (int i = 0; i < 2; i++)
        #pragma unroll
        for (int j = 0; j < 8; j++)
            #pragma unroll
            for (int r = 0; r < 4; r++) acc[i][j][r] = 0.0f;

    const int n0 = blockIdx.x * 128;
    const int m0 = blockIdx.y * 128;
    gemm_tf32(g_xtf, g_wqkv_tf, m0, n0, NC, smemu, acc);

    const int lane = threadIdx.x & 31, wid = threadIdx.x >> 5;
    const int wm = (wid & 3) << 5, wn = (wid >> 2) << 6;
    const int g = lane >> 2, tg = lane & 3;

    #pragma unroll
    for (int mt = 0; mt < 2; mt++) {
        #pragma unroll
        for (int half = 0; half < 2; half++) {
            int m  = m0 + wm + mt * 16 + g + half * 8;
            int bb = m >> 10;
            int l  = m & 1023;
            #pragma unroll
            for (int nt = 0; nt < 8; nt++) {
                int n     = n0 + wn + nt * 8 + 2 * tg;
                int which = n >> 10;           // 0=q 1=k 2=v
                int cc    = n & 1023;
                int h     = cc >> 6;
                int dd    = cc & 63;
                float2 r;
                r.x = acc[mt][nt][half * 2 + 0];
                r.y = acc[mt][nt][half * 2 + 1];
                float* dst;
                if (which == 0) {
                    float2 b2 = *(const float2*)(qb + cc);
                    r.x += b2.x; r.y += b2.y;
                    dst = g_q;
                } else if (which == 1) {
                    dst = g_k;
                } else {
                    float2 b2 = *(const float2*)(vb + cc);
                    r.x += b2.x; r.y += b2.y;
                    dst = g_v;
                }
                *(float2*)(dst + (((size_t)bb * NH + h) * NL + l) * ND + dd) = r;
            }
        }
    }
}

// ---------------- Kernel 2: per-(b,h,l) L2 normalize of q (scaled) and k ----
__global__ void k_norm(const float* __restrict__ scale_mul) {
    const int lane = threadIdx.x & 31;
    const int row  = blockIdx.x * (blockDim.x >> 5) + (threadIdx.x >> 5);
    const int NQ   = NB * NH * NL;
    const bool isq = row < NQ;
    const int r    = isq ? row : row - NQ;
    float* base = (isq ? g_q : g_k) + (size_t)r * ND;
    float2 v = ((float2*)base)[lane];
    float ss = v.x * v.x + v.y * v.y;
    #pragma unroll
    for (int m = 16; m >= 1; m >>= 1)
        ss += __shfl_xor_sync(0xffffffffu, ss, m);
    float mul = 1.0f;
    if (isq) {
        int h = (r >> 10) & 15;
        mul = __expf(fminf(scale_mul[h], 4.605170185988091f)); // log(100)
    }
    float sc = mul / fmaxf(sqrtf(ss), 1e-12f);
    v.x *= sc; v.y *= sc;
    ((float2*)base)[lane] = v;
}

// ---------------- Kernel 3: flash attention (cp.async pipelined) ------------
// QK^T: fp16 m16n8k16, asymmetric split S = Qh.K + Ql.K.
// PV:   fp16 m16n8k16. K/V pre-converted fp16 in gmem -> pure cp.async tiles,
// double-buffered; bias cp.async into smem, hidden under QK MMAs.
#define KP 36                      // f16x2 K-tile pitch (uints per row)
#define VP 36                      // f16x2 V/P pitch (uints per row)
#define BP 68                      // bias tile pitch (floats per row)
// smem word offsets
#define OKF 0                      // 2 x 2304 (K double buffer)
#define OVH 4608                   // 2 x 2304 (V double buffer)
#define OBS 9216                   // 64*68 = 4352 (bias)
#define OPS 13568                  // 64*36 = 2304 (P)
#define ATTN_SMEM ((OPS + 2304) * 4)   // 63488 B

__global__ void __launch_bounds__(128, 3)
k_attn(const float* __restrict__ bias) {
    extern __shared__ unsigned smu[];
    unsigned* Ps = smu + OPS;

    const int t    = threadIdx.x;
    const int lane = t & 31, w = t >> 5;
    const int g = lane >> 2, tg = lane & 3;
    const int bh = blockIdx.y, h = bh & 15;
    const int q0 = blockIdx.x * 64;
    const int r0 = w * 16 + g;        // block-local q row (this thread: r0, r0+8)

    const unsigned sb = smem_u32(smu);
    // ldmatrix lane addressing (bytes)
    const int l15 = lane & 15;
    const int lhi = (lane >> 4) * 16;
    const unsigned kfR = sb + OKF * 4 + (unsigned)(l15 * KP) * 4 + lhi;
    const unsigned vhR = sb + OVH * 4 + (unsigned)(l15 * VP) * 4 + lhi;
    const unsigned psR = sb + OPS * 4 + (unsigned)((w * 16 + l15) * VP) * 4 + lhi;

    // cp.async loader addressing
    const int krow = t >> 3, kc = t & 7;          // wait: need 512 tasks / 128 thr = 4 each
    const unsigned kDst = sb + OKF * 4 + (unsigned)(krow * KP + kc * 4) * 4;
    const unsigned vDst = sb + OVH * 4 + (unsigned)(krow * VP + kc * 4) * 4;
    const unsigned* kSrc = g_kf16 + (size_t)bh * (NL * ND / 2) + (size_t)krow * (ND / 2) + kc * 4;
    const unsigned* vSrc = g_vt16 + (size_t)bh * (ND * NL / 2) + (size_t)krow * (NL / 2) + kc * 4;
    const int brow = t >> 4, bc = t & 15;
    const unsigned bDst = sb + OBS * 4 + (unsigned)(brow * BP + bc * 4) * 4;
    const float* bSrc = bias + (size_t)h * NL * NL + (size_t)(q0 + brow) * NL + bc * 4;

    // Q fragments: f16x2 hi/lo
    unsigned qh[4][4], ql[4][4];
    {
        const float* qbase = g_q + ((size_t)bh * NL + q0) * ND;
        #pragma unroll
        for (int kg = 0; kg < 4; kg++) {
            #pragma unroll
            for (int i = 0; i < 4; i++) {
                int row = r0 + (i & 1) * 8;
                int kk  = kg * 16 + 2 * tg + (i >> 1) * 8;
                float x0 = qbase[(size_t)row * ND + kk];
                float x1 = qbase[(size_t)row * ND + kk + 1];
                qh[kg][i] = pk_f16(x0, x1);
                ql[kg][i] = pk_f16(f16_res(x0), f16_res(x1));
            }
        }
    }

    float o[8][4];
    #pragma unroll
    for (int nt = 0; nt < 8; nt++)
        #pragma unroll
        for (int i = 0; i < 4; i++) o[nt][i] = 0.0f;
    float m0 = -INFINITY, m1 = -INFINITY, l0 = 0.0f, l1 = 0.0f;

    // prologue: KV tile 0 -> buf 0 (K: 64 rows x 4 cpa16/thread; V same)
    #pragma unroll
    for (int i = 0; i < 4; i++) {
        cpa16(kDst + i * (16 * KP * 4), kSrc + (size_t)i * 16 * (ND / 2));
        cpa16(vDst + i * (16 * VP * 4), vSrc + (size_t)i * 16 * (NL / 2));
    }
    cpa_commit();

    for (int jt = 0; jt < 16; jt++) {
        const unsigned bufo = (unsigned)(jt & 1) * (2304 * 4);
        cpa_wait0();                  // KV tile jt resident
        __syncthreads();              // all warps done with prev buffers

        // issue bias jt (group 1), then KV jt+1 (group 2)
        #pragma unroll
        for (int i = 0; i < 8; i++)
            cpa16(bDst + i * (8 * BP * 4), bSrc + jt * 64 + (size_t)i * 8 * NL);
        cpa_commit();
        if (jt < 15) {
            const unsigned nbo = (unsigned)((jt + 1) & 1) * (2304 * 4);
            const unsigned* kS = kSrc + (size_t)(jt + 1) * 64 * (ND / 2);
            const unsigned* vS = vSrc + (jt + 1) * 32;
            #pragma unroll
            for (int i = 0; i < 4; i++) {
                cpa16(kDst + nbo + i * (16 * KP * 4), kS + (size_t)i * 16 * (ND / 2));
                cpa16(vDst + nbo + i * (16 * VP * 4), vS + (size_t)i * 16 * (NL / 2));
            }
        }
        cpa_commit();

        // S = Q K^T : fp16 k16, 2-term asymmetric split
        float s[8][4];
        #pragma unroll
        for (int nt = 0; nt < 8; nt++)
            #pragma unroll
            for (int i = 0; i < 4; i++) s[nt][i] = 0.0f;
        #pragma unroll
        for (int kg = 0; kg < 4; kg++) {
            #pragma unroll
            for (int ntp = 0; ntp < 4; ntp++) {
                unsigned hb[4];
                ldsm4(hb, kfR + bufo + (unsigned)(ntp * 16 * KP + kg * 8) * 4);
                unsigned h0[2] = { hb[0], hb[2] }, h1[2] = { hb[1], hb[3] };
                mma_fp16(s[2*ntp],     qh[kg], h0);
                mma_fp16(s[2*ntp],     ql[kg], h0);
                mma_fp16(s[2*ntp + 1], qh[kg], h1);
                mma_fp16(s[2*ntp + 1], ql[kg], h1);
            }
        }

        cpa_wait1();                  // bias jt resident (KV jt+1 may pend)
        __syncthreads();

        // bias add + tile max (bias from smem)
        const float* Bs = (const float*)(smu + OBS);
        float tm0 = -INFINITY, tm1 = -INFINITY;
        #pragma unroll
        for (int nt = 0; nt < 8; nt++) {
            int col = nt * 8 + 2 * tg;
            float2 b0 = *(const float2*)(Bs + r0 * BP + col);
            float2 b1 = *(const float2*)(Bs + (r0 + 8) * BP + col);
            s[nt][0] += b0.x; s[nt][1] += b0.y;
            s[nt][2] += b1.x; s[nt][3] += b1.y;
            tm0 = fmaxf(tm0, fmaxf(s[nt][0], s[nt][1]));
            tm1 = fmaxf(tm1, fmaxf(s[nt][2], s[nt][3]));
        }
        tm0 = fmaxf(tm0, __shfl_xor_sync(0xffffffffu, tm0, 1));
        tm0 = fmaxf(tm0, __shfl_xor_sync(0xffffffffu, tm0, 2));
        tm1 = fmaxf(tm1, __shfl_xor_sync(0xffffffffu, tm1, 1));
        tm1 = fmaxf(tm1, __shfl_xor_sync(0xffffffffu, tm1, 2));

        float mn0 = fmaxf(m0, tm0), mn1 = fmaxf(m1, tm1);
        float a0 = __expf(m0 - mn0), a1 = __expf(m1 - mn1);
        m0 = mn0; m1 = mn1;
        l0 *= a0; l1 *= a1;
        #pragma unroll
        for (int nt = 0; nt < 8; nt++) {
            o[nt][0] *= a0; o[nt][1] *= a0;
            o[nt][2] *= a1; o[nt][3] *= a1;
        }

        // p = exp(s - m); accumulate l; stage P into smem as f16x2
        #pragma unroll
        for (int nt = 0; nt < 8; nt++) {
            float p0 = __expf(s[nt][0] - m0), p1 = __expf(s[nt][1] - m0);
            float p2 = __expf(s[nt][2] - m1), p3 = __expf(s[nt][3] - m1);
            l0 += p0 + p1; l1 += p2 + p3;
            Ps[r0 * VP + nt * 4 + tg]       = pk_f16(p0, p1);
            Ps[(r0 + 8) * VP + nt * 4 + tg] = pk_f16(p2, p3);
        }
        __syncwarp();                  // Ps rows are warp-private

        // O += P V (fp16 k16)
        #pragma unroll
        for (int kg = 0; kg < 4; kg++) {
            unsigned ap4[4];
            ldsm4(ap4, psR + (unsigned)(kg * 32));
            #pragma unroll
            for (int ntp = 0; ntp < 4; ntp++) {
                unsigned bv4[4];
                ldsm4(bv4, vhR + bufo + (unsigned)(ntp * 16 * VP * 4) + kg * 32);
                unsigned v0[2] = { bv4[0], bv4[2] }, v1[2] = { bv4[1], bv4[3] };
                mma_fp16(o[2*ntp],     ap4, v0);
                mma_fp16(o[2*ntp + 1], ap4, v1);
            }
        }
    }

    // finish l reduction across tg and write out as tf32 bits (proj A operand)
    l0 += __shfl_xor_sync(0xffffffffu, l0, 1);
    l0 += __shfl_xor_sync(0xffffffffu, l0, 2);
    l1 += __shfl_xor_sync(0xffffffffu, l1, 1);
    l1 += __shfl_xor_sync(0xffffffffu, l1, 2);
    float i0 = 1.0f / l0, i1 = 1.0f / l1;

    unsigned* op = g_aotf + ((size_t)(bh >> 4) * NL + q0) * NC + h * ND;
    #pragma unroll
    for (int nt = 0; nt < 8; nt++) {
        int col = nt * 8 + 2 * tg;
        uint2 r0v = make_uint2(f2tf(o[nt][0] * i0), f2tf(o[nt][1] * i0));
        uint2 r1v = make_uint2(f2tf(o[nt][2] * i1), f2tf(o[nt][3] * i1));
        *(uint2*)(op + (size_t)r0 * NC + col)       = r0v;
        *(uint2*)(op + (size_t)(r0 + 8) * NC + col) = r1v;
    }
}

// ---------------- Kernel 4: output projection GEMM + bias -------------------
__global__ void __launch_bounds__(256)
k_proj(const float* __restrict__ bp, float* __restrict__ out) {
    extern __shared__ unsigned smemu[];
    float acc[2][8][4];
    #pragma unroll
    for (int i = 0; i < 2; i++)
        #pragma unroll
        for (int j = 0; j < 8; j++)
            #pragma unroll
            for (int r = 0; r < 4; r++) acc[i][j][r] = 0.0f;

    const int n0 = blockIdx.x * 128;
    const int m0 = blockIdx.y * 128;
    gemm_tf32(g_aotf, g_wproj_tf, m0, n0, NC, smemu, acc);

    const int lane = threadIdx.x & 31, wid = threadIdx.x >> 5;
    const int wm = (wid & 3) << 5, wn = (wid >> 2) << 6;
    const int g = lane >> 2, tg = lane & 3;

    #pragma unroll
    for (int mt = 0; mt < 2; mt++) {
        #pragma unroll
        for (int half = 0; half < 2; half++) {
            int m = m0 + wm + mt * 16 + g + half * 8;
            #pragma unroll
            for (int nt = 0; nt < 8; nt++) {
                int n = n0 + wn + nt * 8 + 2 * tg;
                float2 b2 = *(const float2*)(bp + n);
                float2 r;
                r.x = acc[mt][nt][half * 2 + 0] + b2.x;
                r.y = acc[mt][nt][half * 2 + 1] + b2.y;
                *(float2*)(out + (size_t)m * NC + n) = r;
            }
        }
    }
}

// ---------------- host launcher ---------------------------------------------
extern "C" void kernel_launch(void* const* d_in, const int* in_sizes, int n_in,
                              void* d_out, int out_size) {
    const float* x         = (const float*)d_in[0];
    const float* attn_bias = (const float*)d_in[1];
    const float* w_qkv     = (const float*)d_in[2];
    const float* q_bias    = (const float*)d_in[3];
    const float* v_bias    = (const float*)d_in[4];
    const float* scale_mul = (const float*)d_in[5];
    const float* w_proj    = (const float*)d_in[6];
    const float* b_proj    = (const float*)d_in[7];
    float* out = (float*)d_out;

    cudaFuncSetAttribute(k_qkv,  cudaFuncAttributeMaxDynamicSharedMemorySize, GEMM_SMEM);
    cudaFuncSetAttribute(k_proj, cudaFuncAttributeMaxDynamicSharedMemorySize, GEMM_SMEM);
    cudaFuncSetAttribute(k_attn, cudaFuncAttributeMaxDynamicSharedMemorySize, ATTN_SMEM);

    // tf32 pre-conversion of x, w_qkv, w_proj (feeds cp.async GEMMs)
    k_cvt3<<<12288, 256>>>((const float4*)x, (const float4*)w_qkv,
                           (const float4*)w_proj);

    // QKV projection: [8192,1024] x [3072,1024]^T, cp.async 3-stage TF32
    k_qkv<<<dim3(24, 64), 256, GEMM_SMEM>>>(q_bias, v_bias);

    // L2-normalize q (with exp(min(scale,log100)) scale) and k
    k_norm<<<32768, 256>>>(scale_mul);

    // K -> f16x2 linear; V -> f16x2 transposed [bh][d][l/2]
    k_prep_k16<<<8192, 256>>>();
    k_prep_vt<<<2048, 256>>>();

    // attention: pipelined fp16 flash attention, 64-row q tiles
    k_attn<<<dim3(16, 128), 128, ATTN_SMEM>>>(attn_bias);

    // output projection: [8192,1024] x [1024,1024]^T, cp.async 3-stage TF32
    k_proj<<<dim3(8, 64), 256, GEMM_SMEM>>>(b_proj, out);
}